// round 12
// baseline (speedup 1.0000x reference)
#include <cuda_runtime.h>
#include <math.h>

// Problem constants
#define BSZ   4
#define SSZ   2048
#define DM    1024
#define HH    16
#define DHD   64
#define DFF_  4096
#define LNUM  6
#define MS    (BSZ*SSZ)   // 8192 rows

// ---------------------------------------------------------------------------
// Scratch (device globals — no allocation allowed)
// ---------------------------------------------------------------------------
__device__ float g_X[MS*DM];     // running activations
__device__ float g_Q[MS*DM];
__device__ float g_K[MS*DM];
__device__ float g_V[MS*DM];
__device__ float g_T[MS*DM];     // attn output / ffn tmp
__device__ float g_F[(size_t)MS*DFF_];   // ffn hidden
__device__ float g_KV[BSZ*HH*DHD*DHD];
__device__ float g_KS[BSZ*HH*DHD];

// ---------------------------------------------------------------------------
// copy x -> g_X
// ---------------------------------------------------------------------------
__global__ void __launch_bounds__(256) copy_kernel(const float* __restrict__ src,
                                                   float* __restrict__ dst)
{
    size_t i = ((size_t)blockIdx.x * 256 + threadIdx.x) * 4;
    *(float4*)(dst + i) = *(const float4*)(src + i);
}

// ---------------------------------------------------------------------------
// Tiled SGEMM: C[M,N] = act(A[M,K] @ W[K,N] + bias[N])
// ACT: 0 = none, 1 = elu+1 (phi), 2 = relu
// BM=BN=128, BK=16, 256 threads, 8x8 per-thread microtile.
// ---------------------------------------------------------------------------
template<int ACT>
__global__ void __launch_bounds__(256) gemm_kernel(
    const float* __restrict__ A, const float* __restrict__ W,
    const float* __restrict__ bias, float* __restrict__ C,
    int M, int N, int K)
{
    __shared__ float As[16][128];   // A^T tile: As[k][m]
    __shared__ float Bs[16][128];   // Bs[k][n]

    const int tid = threadIdx.x;
    const int bx = blockIdx.x;      // N tile
    const int by = blockIdx.y;      // M tile

    const float* Ab = A + (size_t)by * 128 * K;
    const float* Wb = W + (size_t)bx * 128;

    const int ty = tid >> 4, tx = tid & 15;
    const int row0 = ty * 8, col0 = tx * 8;

    float acc[8][8];
#pragma unroll
    for (int i = 0; i < 8; i++)
#pragma unroll
        for (int j = 0; j < 8; j++) acc[i][j] = 0.f;

    for (int k0 = 0; k0 < K; k0 += 16) {
#pragma unroll
        for (int j = 0; j < 2; j++) {
            int idx = tid + j * 256;          // 0..511
            // A tile: 128 rows x 16 cols  = 512 float4 (4 per row)
            int r  = idx >> 2;
            int c4 = (idx & 3) * 4;
            float4 va = *(const float4*)(Ab + (size_t)r * K + k0 + c4);
            As[c4 + 0][r] = va.x;
            As[c4 + 1][r] = va.y;
            As[c4 + 2][r] = va.z;
            As[c4 + 3][r] = va.w;
            // B tile: 16 rows x 128 cols = 512 float4 (32 per row)
            int kr = idx >> 5;
            int n4 = (idx & 31) * 4;
            float4 vb = *(const float4*)(Wb + (size_t)(k0 + kr) * N + n4);
            *(float4*)&Bs[kr][n4] = vb;
        }
        __syncthreads();

#pragma unroll
        for (int kk = 0; kk < 16; kk++) {
            float a[8], bb[8];
            *(float4*)&a[0]  = *(const float4*)&As[kk][row0];
            *(float4*)&a[4]  = *(const float4*)&As[kk][row0 + 4];
            *(float4*)&bb[0] = *(const float4*)&Bs[kk][col0];
            *(float4*)&bb[4] = *(const float4*)&Bs[kk][col0 + 4];
#pragma unroll
            for (int i = 0; i < 8; i++)
#pragma unroll
                for (int j = 0; j < 8; j++)
                    acc[i][j] = fmaf(a[i], bb[j], acc[i][j]);
        }
        __syncthreads();
    }

    float bj[8];
#pragma unroll
    for (int j = 0; j < 8; j++) bj[j] = bias[bx * 128 + col0 + j];

    float* Cb = C + (size_t)(by * 128) * N + bx * 128;
#pragma unroll
    for (int i = 0; i < 8; i++) {
        float o[8];
#pragma unroll
        for (int j = 0; j < 8; j++) {
            float v = acc[i][j] + bj[j];
            if (ACT == 1) v = (v > 0.f) ? (v + 1.f) : __expf(v);  // elu(v)+1
            if (ACT == 2) v = fmaxf(v, 0.f);
            o[j] = v;
        }
        *(float4*)(Cb + (size_t)(row0 + i) * N + col0)     = *(float4*)&o[0];
        *(float4*)(Cb + (size_t)(row0 + i) * N + col0 + 4) = *(float4*)&o[4];
    }
}

// ---------------------------------------------------------------------------
// kv[b,h,d,m] = sum_s k[b,s,h,d] * v[b,s,h,m];  ksum[b,h,d] = sum_s k[b,s,h,d]
// grid = B*H blocks, 256 threads; each thread owns a 4x4 tile of the 64x64 kv.
// ---------------------------------------------------------------------------
__global__ void __launch_bounds__(256) kv_reduce_kernel(
    const float* __restrict__ Kx, const float* __restrict__ Vx,
    float* __restrict__ KVo, float* __restrict__ KSo)
{
    const int bh = blockIdx.x;
    const int b = bh >> 4, h = bh & 15;
    const float* Kb = Kx + (size_t)b * SSZ * DM + h * DHD;
    const float* Vb = Vx + (size_t)b * SSZ * DM + h * DHD;

    __shared__ float ks[32][64];
    __shared__ float vs[32][64];

    const int tid = threadIdx.x;
    const int ty = tid >> 4, tx = tid & 15;

    float acc[4][4] = {};
    float ksum = 0.f;

    for (int s0 = 0; s0 < SSZ; s0 += 32) {
#pragma unroll
        for (int j = 0; j < 2; j++) {
            int idx = tid + j * 256;
            int r = idx >> 4, c4 = (idx & 15) * 4;
            *(float4*)&ks[r][c4] = *(const float4*)(Kb + (size_t)(s0 + r) * DM + c4);
            *(float4*)&vs[r][c4] = *(const float4*)(Vb + (size_t)(s0 + r) * DM + c4);
        }
        __syncthreads();

#pragma unroll 8
        for (int s = 0; s < 32; s++) {
            float a[4], bv[4];
#pragma unroll
            for (int i = 0; i < 4; i++) a[i] = ks[s][ty * 4 + i];
#pragma unroll
            for (int j = 0; j < 4; j++) bv[j] = vs[s][tx * 4 + j];
#pragma unroll
            for (int i = 0; i < 4; i++)
#pragma unroll
                for (int j = 0; j < 4; j++)
                    acc[i][j] = fmaf(a[i], bv[j], acc[i][j]);
        }
        if (tid < 64) {
#pragma unroll 8
            for (int s = 0; s < 32; s++) ksum += ks[s][tid];
        }
        __syncthreads();
    }

    float* KVb = KVo + (size_t)bh * DHD * DHD;
#pragma unroll
    for (int i = 0; i < 4; i++)
#pragma unroll
        for (int j = 0; j < 4; j++)
            KVb[(ty * 4 + i) * DHD + tx * 4 + j] = acc[i][j];
    if (tid < 64) KSo[bh * DHD + tid] = ksum;
}

// ---------------------------------------------------------------------------
// o[b,s,h,m] = z * sum_d q[b,s,h,d] * kv[b,h,d,m],  z = 1/(q . ksum + 1e-6)
// grid = (B*H, S/64), 256 threads; 64 q-rows per block, 16 out cols per thread.
// ---------------------------------------------------------------------------
__global__ void __launch_bounds__(256) attn_out_kernel(
    const float* __restrict__ Qx, const float* __restrict__ KVi,
    const float* __restrict__ KSi, float* __restrict__ O)
{
    const int bh = blockIdx.x;
    const int b = bh >> 4, h = bh & 15;
    const int s0 = blockIdx.y * 64;

    __shared__ float qs[64][64];
    __shared__ float kvs[64][64];
    __shared__ float kss[64];

    const int tid = threadIdx.x;
    const float* Qb  = Qx + (size_t)(b * SSZ + s0) * DM + h * DHD;
    const float* KVb = KVi + (size_t)bh * DHD * DHD;

#pragma unroll
    for (int j = 0; j < 4; j++) {
        int idx = tid + j * 256;
        int r = idx >> 4, c4 = (idx & 15) * 4;
        *(float4*)&qs[r][c4]  = *(const float4*)(Qb + (size_t)r * DM + c4);
        *(float4*)&kvs[r][c4] = *(const float4*)(KVb + r * DHD + c4);
    }
    if (tid < 64) kss[tid] = KSi[bh * DHD + tid];
    __syncthreads();

    const int row = tid >> 2;
    const int mo  = (tid & 3) * 16;

    float z = 0.f;
#pragma unroll
    for (int d = 0; d < 64; d++) z = fmaf(qs[row][d], kss[d], z);
    z = 1.f / (z + 1e-6f);

    float acc[16] = {};
#pragma unroll
    for (int d = 0; d < 64; d++) {
        float qd = qs[row][d];
#pragma unroll
        for (int m = 0; m < 16; m++)
            acc[m] = fmaf(qd, kvs[d][mo + m], acc[m]);
    }

    float* Ob = O + (size_t)(b * SSZ + s0 + row) * DM + h * DHD + mo;
#pragma unroll
    for (int m = 0; m < 16; m++) acc[m] *= z;
#pragma unroll
    for (int q4 = 0; q4 < 4; q4++)
        *(float4*)(Ob + q4 * 4) = *(float4*)&acc[q4 * 4];
}

// ---------------------------------------------------------------------------
// out = LayerNorm(X (+ Y)) * w + b  over last dim (1024). One block per row.
// ---------------------------------------------------------------------------
__global__ void __launch_bounds__(256) ln_kernel(
    const float* X, const float* Yr, const float* __restrict__ w,
    const float* __restrict__ bb, float* out, int has_res)
{
    __shared__ float ss[8], ssq[8];
    __shared__ float sm, sr;

    const int row = blockIdx.x;
    const int tid = threadIdx.x;
    const int c = tid * 4;

    float4 xv = *(const float4*)(X + (size_t)row * DM + c);
    float v0 = xv.x, v1 = xv.y, v2 = xv.z, v3 = xv.w;
    if (has_res) {
        float4 yv = *(const float4*)(Yr + (size_t)row * DM + c);
        v0 += yv.x; v1 += yv.y; v2 += yv.z; v3 += yv.w;
    }

    float s  = v0 + v1 + v2 + v3;
    float sq = v0 * v0 + v1 * v1 + v2 * v2 + v3 * v3;
#pragma unroll
    for (int off = 16; off; off >>= 1) {
        s  += __shfl_xor_sync(0xffffffffu, s,  off);
        sq += __shfl_xor_sync(0xffffffffu, sq, off);
    }
    const int wid = tid >> 5, lane = tid & 31;
    if (lane == 0) { ss[wid] = s; ssq[wid] = sq; }
    __syncthreads();
    if (tid == 0) {
        float t = 0.f, tq = 0.f;
#pragma unroll
        for (int i = 0; i < 8; i++) { t += ss[i]; tq += ssq[i]; }
        float mean = t * (1.f / DM);
        float var  = tq * (1.f / DM) - mean * mean;
        sm = mean;
        sr = rsqrtf(var + 1e-5f);
    }
    __syncthreads();
    const float mean = sm, rstd = sr;

    float4 wv = *(const float4*)(w + c);
    float4 bv = *(const float4*)(bb + c);
    float4 ov;
    ov.x = (v0 - mean) * rstd * wv.x + bv.x;
    ov.y = (v1 - mean) * rstd * wv.y + bv.y;
    ov.z = (v2 - mean) * rstd * wv.z + bv.z;
    ov.w = (v3 - mean) * rstd * wv.w + bv.w;
    *(float4*)(out + (size_t)row * DM + c) = ov;
}

// ---------------------------------------------------------------------------
// Orchestration
// ---------------------------------------------------------------------------
extern "C" void kernel_launch(void* const* d_in, const int* in_sizes, int n_in,
                              void* d_out, int out_size)
{
    const float* x    = (const float*)d_in[0];
    const float* Wq   = (const float*)d_in[1];
    const float* bq   = (const float*)d_in[2];
    const float* Wk   = (const float*)d_in[3];
    const float* bk   = (const float*)d_in[4];
    const float* Wv   = (const float*)d_in[5];
    const float* bv   = (const float*)d_in[6];
    const float* Wo   = (const float*)d_in[7];
    const float* bo   = (const float*)d_in[8];
    const float* ln1w = (const float*)d_in[9];
    const float* ln1b = (const float*)d_in[10];
    const float* W1   = (const float*)d_in[11];
    const float* b1   = (const float*)d_in[12];
    const float* W2   = (const float*)d_in[13];
    const float* b2   = (const float*)d_in[14];
    const float* ln2w = (const float*)d_in[15];
    const float* ln2b = (const float*)d_in[16];
    const float* lnfw = (const float*)d_in[17];
    const float* lnfb = (const float*)d_in[18];

    float *X, *Q, *Kb, *Vb, *T, *F, *KV, *KS;
    cudaGetSymbolAddress((void**)&X,  g_X);
    cudaGetSymbolAddress((void**)&Q,  g_Q);
    cudaGetSymbolAddress((void**)&Kb, g_K);
    cudaGetSymbolAddress((void**)&Vb, g_V);
    cudaGetSymbolAddress((void**)&T,  g_T);
    cudaGetSymbolAddress((void**)&F,  g_F);
    cudaGetSymbolAddress((void**)&KV, g_KV);
    cudaGetSymbolAddress((void**)&KS, g_KS);

    copy_kernel<<<(MS * DM) / 1024, 256>>>(x, X);

    const dim3 gD(DM / 128, MS / 128);      // (8, 64)  for N=1024
    const dim3 gF1(DFF_ / 128, MS / 128);   // (32, 64) for N=4096

    for (int l = 0; l < LNUM; l++) {
        const float* wq = Wq + (size_t)l * DM * DM;
        const float* wk = Wk + (size_t)l * DM * DM;
        const float* wv = Wv + (size_t)l * DM * DM;
        const float* wo = Wo + (size_t)l * DM * DM;
        const float* w1 = W1 + (size_t)l * DM * DFF_;
        const float* w2 = W2 + (size_t)l * DFF_ * DM;
        const float* bqL = bq + (size_t)l * DM;
        const float* bkL = bk + (size_t)l * DM;
        const float* bvL = bv + (size_t)l * DM;
        const float* boL = bo + (size_t)l * DM;
        const float* b1L = b1 + (size_t)l * DFF_;
        const float* b2L = b2 + (size_t)l * DM;
        const float* l1w = ln1w + (size_t)l * DM;
        const float* l1b = ln1b + (size_t)l * DM;
        const float* l2w = ln2w + (size_t)l * DM;
        const float* l2b = ln2b + (size_t)l * DM;

        // Q = phi(X Wq + bq), K = phi(X Wk + bk), V = X Wv + bv
        gemm_kernel<1><<<gD, 256>>>(X, wq, bqL, Q,  MS, DM, DM);
        gemm_kernel<1><<<gD, 256>>>(X, wk, bkL, Kb, MS, DM, DM);
        gemm_kernel<0><<<gD, 256>>>(X, wv, bvL, Vb, MS, DM, DM);

        // kv, ksum
        kv_reduce_kernel<<<BSZ * HH, 256>>>(Kb, Vb, KV, KS);

        // attn out (pre-projection) -> T
        attn_out_kernel<<<dim3(BSZ * HH, SSZ / 64), 256>>>(Q, KV, KS, T);

        // projection -> Vb (free now), then X = LN1(X + Vb)
        gemm_kernel<0><<<gD, 256>>>(T, wo, boL, Vb, MS, DM, DM);
        ln_kernel<<<MS, 256>>>(X, Vb, l1w, l1b, X, 1);

        // FFN: F = relu(X W1 + b1); T = F W2 + b2; X = LN2(X + T)
        gemm_kernel<2><<<gF1, 256>>>(X, w1, b1L, F, MS, DFF_, DM);
        gemm_kernel<0><<<gD, 256>>>(F, w2, b2L, T, MS, DM, DFF_);
        ln_kernel<<<MS, 256>>>(X, T, l2w, l2b, X, 1);
    }

    // final LayerNorm -> d_out
    ln_kernel<<<MS, 256>>>(X, X, lnfw, lnfb, (float*)d_out, 0);
}

// round 13
// speedup vs baseline: 1.0008x; 1.0008x over previous
#include <cuda_runtime.h>
#include <math.h>

// Problem constants
#define BSZ   4
#define SSZ   2048
#define DM    1024
#define HH    16
#define DHD   64
#define DFF_  4096
#define LNUM  6
#define MS    (BSZ*SSZ)   // 8192 rows

// ---------------------------------------------------------------------------
// Scratch (device globals — no allocation allowed)
// ---------------------------------------------------------------------------
__device__ float g_X[MS*DM];     // running activations
__device__ float g_Q[MS*DM];
__device__ float g_K[MS*DM];
__device__ float g_V[MS*DM];
__device__ float g_T[MS*DM];     // attn output / ffn tmp
__device__ float g_F[(size_t)MS*DFF_];   // ffn hidden
__device__ float g_KV[BSZ*HH*DHD*DHD];
__device__ float g_KS[BSZ*HH*DHD];

// ---------------------------------------------------------------------------
// copy x -> g_X
// ---------------------------------------------------------------------------
__global__ void __launch_bounds__(256) copy_kernel(const float* __restrict__ src,
                                                   float* __restrict__ dst)
{
    size_t i = ((size_t)blockIdx.x * 256 + threadIdx.x) * 4;
    *(float4*)(dst + i) = *(const float4*)(src + i);
}

// ---------------------------------------------------------------------------
// Tiled SGEMM: C[M,N] = act(A[M,K] @ W[K,N] + bias[N])
// ACT: 0 = none, 1 = elu+1 (phi), 2 = relu
// BM=BN=128, BK=16, 256 threads, 8x8 per-thread microtile.
// ---------------------------------------------------------------------------
template<int ACT>
__global__ void __launch_bounds__(256) gemm_kernel(
    const float* __restrict__ A, const float* __restrict__ W,
    const float* __restrict__ bias, float* __restrict__ C,
    int M, int N, int K)
{
    __shared__ float As[16][128];   // A^T tile: As[k][m]
    __shared__ float Bs[16][128];   // Bs[k][n]

    const int tid = threadIdx.x;
    const int bx = blockIdx.x;      // N tile
    const int by = blockIdx.y;      // M tile

    const float* Ab = A + (size_t)by * 128 * K;
    const float* Wb = W + (size_t)bx * 128;

    const int ty = tid >> 4, tx = tid & 15;
    const int row0 = ty * 8, col0 = tx * 8;

    float acc[8][8];
#pragma unroll
    for (int i = 0; i < 8; i++)
#pragma unroll
        for (int j = 0; j < 8; j++) acc[i][j] = 0.f;

    for (int k0 = 0; k0 < K; k0 += 16) {
#pragma unroll
        for (int j = 0; j < 2; j++) {
            int idx = tid + j * 256;          // 0..511
            // A tile: 128 rows x 16 cols  = 512 float4 (4 per row)
            int r  = idx >> 2;
            int c4 = (idx & 3) * 4;
            float4 va = *(const float4*)(Ab + (size_t)r * K + k0 + c4);
            As[c4 + 0][r] = va.x;
            As[c4 + 1][r] = va.y;
            As[c4 + 2][r] = va.z;
            As[c4 + 3][r] = va.w;
            // B tile: 16 rows x 128 cols = 512 float4 (32 per row)
            int kr = idx >> 5;
            int n4 = (idx & 31) * 4;
            float4 vb = *(const float4*)(Wb + (size_t)(k0 + kr) * N + n4);
            *(float4*)&Bs[kr][n4] = vb;
        }
        __syncthreads();

#pragma unroll
        for (int kk = 0; kk < 16; kk++) {
            float a[8], bb[8];
            *(float4*)&a[0]  = *(const float4*)&As[kk][row0];
            *(float4*)&a[4]  = *(const float4*)&As[kk][row0 + 4];
            *(float4*)&bb[0] = *(const float4*)&Bs[kk][col0];
            *(float4*)&bb[4] = *(const float4*)&Bs[kk][col0 + 4];
#pragma unroll
            for (int i = 0; i < 8; i++)
#pragma unroll
                for (int j = 0; j < 8; j++)
                    acc[i][j] = fmaf(a[i], bb[j], acc[i][j]);
        }
        __syncthreads();
    }

    float bj[8];
#pragma unroll
    for (int j = 0; j < 8; j++) bj[j] = bias[bx * 128 + col0 + j];

    float* Cb = C + (size_t)(by * 128) * N + bx * 128;
#pragma unroll
    for (int i = 0; i < 8; i++) {
        float o[8];
#pragma unroll
        for (int j = 0; j < 8; j++) {
            float v = acc[i][j] + bj[j];
            if (ACT == 1) v = (v > 0.f) ? (v + 1.f) : __expf(v);  // elu(v)+1
            if (ACT == 2) v = fmaxf(v, 0.f);
            o[j] = v;
        }
        *(float4*)(Cb + (size_t)(row0 + i) * N + col0)     = *(float4*)&o[0];
        *(float4*)(Cb + (size_t)(row0 + i) * N + col0 + 4) = *(float4*)&o[4];
    }
}

// ---------------------------------------------------------------------------
// kv[b,h,d,m] = sum_s k[b,s,h,d] * v[b,s,h,m];  ksum[b,h,d] = sum_s k[b,s,h,d]
// grid = B*H blocks, 256 threads; each thread owns a 4x4 tile of the 64x64 kv.
// ---------------------------------------------------------------------------
__global__ void __launch_bounds__(256) kv_reduce_kernel(
    const float* __restrict__ Kx, const float* __restrict__ Vx,
    float* __restrict__ KVo, float* __restrict__ KSo)
{
    const int bh = blockIdx.x;
    const int b = bh >> 4, h = bh & 15;
    const float* Kb = Kx + (size_t)b * SSZ * DM + h * DHD;
    const float* Vb = Vx + (size_t)b * SSZ * DM + h * DHD;

    __shared__ float ks[32][64];
    __shared__ float vs[32][64];

    const int tid = threadIdx.x;
    const int ty = tid >> 4, tx = tid & 15;

    float acc[4][4] = {};
    float ksum = 0.f;

    for (int s0 = 0; s0 < SSZ; s0 += 32) {
#pragma unroll
        for (int j = 0; j < 2; j++) {
            int idx = tid + j * 256;
            int r = idx >> 4, c4 = (idx & 15) * 4;
            *(float4*)&ks[r][c4] = *(const float4*)(Kb + (size_t)(s0 + r) * DM + c4);
            *(float4*)&vs[r][c4] = *(const float4*)(Vb + (size_t)(s0 + r) * DM + c4);
        }
        __syncthreads();

#pragma unroll 8
        for (int s = 0; s < 32; s++) {
            float a[4], bv[4];
#pragma unroll
            for (int i = 0; i < 4; i++) a[i] = ks[s][ty * 4 + i];
#pragma unroll
            for (int j = 0; j < 4; j++) bv[j] = vs[s][tx * 4 + j];
#pragma unroll
            for (int i = 0; i < 4; i++)
#pragma unroll
                for (int j = 0; j < 4; j++)
                    acc[i][j] = fmaf(a[i], bv[j], acc[i][j]);
        }
        if (tid < 64) {
#pragma unroll 8
            for (int s = 0; s < 32; s++) ksum += ks[s][tid];
        }
        __syncthreads();
    }

    float* KVb = KVo + (size_t)bh * DHD * DHD;
#pragma unroll
    for (int i = 0; i < 4; i++)
#pragma unroll
        for (int j = 0; j < 4; j++)
            KVb[(ty * 4 + i) * DHD + tx * 4 + j] = acc[i][j];
    if (tid < 64) KSo[bh * DHD + tid] = ksum;
}

// ---------------------------------------------------------------------------
// o[b,s,h,m] = z * sum_d q[b,s,h,d] * kv[b,h,d,m],  z = 1/(q . ksum + 1e-6)
// grid = (B*H, S/64), 256 threads; 64 q-rows per block, 16 out cols per thread.
// ---------------------------------------------------------------------------
__global__ void __launch_bounds__(256) attn_out_kernel(
    const float* __restrict__ Qx, const float* __restrict__ KVi,
    const float* __restrict__ KSi, float* __restrict__ O)
{
    const int bh = blockIdx.x;
    const int b = bh >> 4, h = bh & 15;
    const int s0 = blockIdx.y * 64;

    __shared__ float qs[64][64];
    __shared__ float kvs[64][64];
    __shared__ float kss[64];

    const int tid = threadIdx.x;
    const float* Qb  = Qx + (size_t)(b * SSZ + s0) * DM + h * DHD;
    const float* KVb = KVi + (size_t)bh * DHD * DHD;

#pragma unroll
    for (int j = 0; j < 4; j++) {
        int idx = tid + j * 256;
        int r = idx >> 4, c4 = (idx & 15) * 4;
        *(float4*)&qs[r][c4]  = *(const float4*)(Qb + (size_t)r * DM + c4);
        *(float4*)&kvs[r][c4] = *(const float4*)(KVb + r * DHD + c4);
    }
    if (tid < 64) kss[tid] = KSi[bh * DHD + tid];
    __syncthreads();

    const int row = tid >> 2;
    const int mo  = (tid & 3) * 16;

    float z = 0.f;
#pragma unroll
    for (int d = 0; d < 64; d++) z = fmaf(qs[row][d], kss[d], z);
    z = 1.f / (z + 1e-6f);

    float acc[16] = {};
#pragma unroll
    for (int d = 0; d < 64; d++) {
        float qd = qs[row][d];
#pragma unroll
        for (int m = 0; m < 16; m++)
            acc[m] = fmaf(qd, kvs[d][mo + m], acc[m]);
    }

    float* Ob = O + (size_t)(b * SSZ + s0 + row) * DM + h * DHD + mo;
#pragma unroll
    for (int m = 0; m < 16; m++) acc[m] *= z;
#pragma unroll
    for (int q4 = 0; q4 < 4; q4++)
        *(float4*)(Ob + q4 * 4) = *(float4*)&acc[q4 * 4];
}

// ---------------------------------------------------------------------------
// out = LayerNorm(X (+ Y)) * w + b  over last dim (1024). One block per row.
// ---------------------------------------------------------------------------
__global__ void __launch_bounds__(256) ln_kernel(
    const float* X, const float* Yr, const float* __restrict__ w,
    const float* __restrict__ bb, float* out, int has_res)
{
    __shared__ float ss[8], ssq[8];
    __shared__ float sm, sr;

    const int row = blockIdx.x;
    const int tid = threadIdx.x;
    const int c = tid * 4;

    float4 xv = *(const float4*)(X + (size_t)row * DM + c);
    float v0 = xv.x, v1 = xv.y, v2 = xv.z, v3 = xv.w;
    if (has_res) {
        float4 yv = *(const float4*)(Yr + (size_t)row * DM + c);
        v0 += yv.x; v1 += yv.y; v2 += yv.z; v3 += yv.w;
    }

    float s  = v0 + v1 + v2 + v3;
    float sq = v0 * v0 + v1 * v1 + v2 * v2 + v3 * v3;
#pragma unroll
    for (int off = 16; off; off >>= 1) {
        s  += __shfl_xor_sync(0xffffffffu, s,  off);
        sq += __shfl_xor_sync(0xffffffffu, sq, off);
    }
    const int wid = tid >> 5, lane = tid & 31;
    if (lane == 0) { ss[wid] = s; ssq[wid] = sq; }
    __syncthreads();
    if (tid == 0) {
        float t = 0.f, tq = 0.f;
#pragma unroll
        for (int i = 0; i < 8; i++) { t += ss[i]; tq += ssq[i]; }
        float mean = t * (1.f / DM);
        float var  = tq * (1.f / DM) - mean * mean;
        sm = mean;
        sr = rsqrtf(var + 1e-5f);
    }
    __syncthreads();
    const float mean = sm, rstd = sr;

    float4 wv = *(const float4*)(w + c);
    float4 bv = *(const float4*)(bb + c);
    float4 ov;
    ov.x = (v0 - mean) * rstd * wv.x + bv.x;
    ov.y = (v1 - mean) * rstd * wv.y + bv.y;
    ov.z = (v2 - mean) * rstd * wv.z + bv.z;
    ov.w = (v3 - mean) * rstd * wv.w + bv.w;
    *(float4*)(out + (size_t)row * DM + c) = ov;
}

// ---------------------------------------------------------------------------
// Orchestration
// ---------------------------------------------------------------------------
extern "C" void kernel_launch(void* const* d_in, const int* in_sizes, int n_in,
                              void* d_out, int out_size)
{
    const float* x    = (const float*)d_in[0];
    const float* Wq   = (const float*)d_in[1];
    const float* bq   = (const float*)d_in[2];
    const float* Wk   = (const float*)d_in[3];
    const float* bk   = (const float*)d_in[4];
    const float* Wv   = (const float*)d_in[5];
    const float* bv   = (const float*)d_in[6];
    const float* Wo   = (const float*)d_in[7];
    const float* bo   = (const float*)d_in[8];
    const float* ln1w = (const float*)d_in[9];
    const float* ln1b = (const float*)d_in[10];
    const float* W1   = (const float*)d_in[11];
    const float* b1   = (const float*)d_in[12];
    const float* W2   = (const float*)d_in[13];
    const float* b2   = (const float*)d_in[14];
    const float* ln2w = (const float*)d_in[15];
    const float* ln2b = (const float*)d_in[16];
    const float* lnfw = (const float*)d_in[17];
    const float* lnfb = (const float*)d_in[18];

    float *X, *Q, *Kb, *Vb, *T, *F, *KV, *KS;
    cudaGetSymbolAddress((void**)&X,  g_X);
    cudaGetSymbolAddress((void**)&Q,  g_Q);
    cudaGetSymbolAddress((void**)&Kb, g_K);
    cudaGetSymbolAddress((void**)&Vb, g_V);
    cudaGetSymbolAddress((void**)&T,  g_T);
    cudaGetSymbolAddress((void**)&F,  g_F);
    cudaGetSymbolAddress((void**)&KV, g_KV);
    cudaGetSymbolAddress((void**)&KS, g_KS);

    copy_kernel<<<(MS * DM) / 1024, 256>>>(x, X);

    const dim3 gD(DM / 128, MS / 128);      // (8, 64)  for N=1024
    const dim3 gF1(DFF_ / 128, MS / 128);   // (32, 64) for N=4096

    for (int l = 0; l < LNUM; l++) {
        const float* wq = Wq + (size_t)l * DM * DM;
        const float* wk = Wk + (size_t)l * DM * DM;
        const float* wv = Wv + (size_t)l * DM * DM;
        const float* wo = Wo + (size_t)l * DM * DM;
        const float* w1 = W1 + (size_t)l * DM * DFF_;
        const float* w2 = W2 + (size_t)l * DFF_ * DM;
        const float* bqL = bq + (size_t)l * DM;
        const float* bkL = bk + (size_t)l * DM;
        const float* bvL = bv + (size_t)l * DM;
        const float* boL = bo + (size_t)l * DM;
        const float* b1L = b1 + (size_t)l * DFF_;
        const float* b2L = b2 + (size_t)l * DM;
        const float* l1w = ln1w + (size_t)l * DM;
        const float* l1b = ln1b + (size_t)l * DM;
        const float* l2w = ln2w + (size_t)l * DM;
        const float* l2b = ln2b + (size_t)l * DM;

        // Q = phi(X Wq + bq), K = phi(X Wk + bk), V = X Wv + bv
        gemm_kernel<1><<<gD, 256>>>(X, wq, bqL, Q,  MS, DM, DM);
        gemm_kernel<1><<<gD, 256>>>(X, wk, bkL, Kb, MS, DM, DM);
        gemm_kernel<0><<<gD, 256>>>(X, wv, bvL, Vb, MS, DM, DM);

        // kv, ksum
        kv_reduce_kernel<<<BSZ * HH, 256>>>(Kb, Vb, KV, KS);

        // attn out (pre-projection) -> T
        attn_out_kernel<<<dim3(BSZ * HH, SSZ / 64), 256>>>(Q, KV, KS, T);

        // projection -> Vb (free now), then X = LN1(X + Vb)
        gemm_kernel<0><<<gD, 256>>>(T, wo, boL, Vb, MS, DM, DM);
        ln_kernel<<<MS, 256>>>(X, Vb, l1w, l1b, X, 1);

        // FFN: F = relu(X W1 + b1); T = F W2 + b2; X = LN2(X + T)
        gemm_kernel<2><<<gF1, 256>>>(X, w1, b1L, F, MS, DFF_, DM);
        gemm_kernel<0><<<gD, 256>>>(F, w2, b2L, T, MS, DM, DFF_);
        ln_kernel<<<MS, 256>>>(X, T, l2w, l2b, X, 1);
    }

    // final LayerNorm -> d_out
    ln_kernel<<<MS, 256>>>(X, X, lnfw, lnfb, (float*)d_out, 0);
}

// round 15
// speedup vs baseline: 2.5255x; 2.5234x over previous
#include <cuda_runtime.h>
#include <cuda_bf16.h>
#include <math.h>
#include <stdint.h>

// Problem constants
#define BSZ   4
#define SSZ   2048
#define DM    1024
#define HH    16
#define DHD   64
#define DFF_  4096
#define LNUM  6
#define MS    (BSZ*SSZ)   // 8192 rows

// GEMM tiling (Ampere-style mma.sync path; tcgen05 unavailable on compute_103)
#define BM 128
#define BN 128
#define BK 32
#define GT 512                 // 16 warps
#define NSTG 3
#define STG_BYTES 32768        // Ah/Al/Bh/Bl: 4 x 8192 B
#define OFF_AH 0
#define OFF_AL 8192
#define OFF_BH 16384
#define OFF_BL 24576
#define BIAS_BYTES 512
#define SMEM_G (BIAS_BYTES + NSTG*STG_BYTES)   // 98816 B

// ---------------------------------------------------------------------------
// Scratch (device globals — no allocation allowed)
// ---------------------------------------------------------------------------
__device__ float g_X[MS*DM];                 // residual stream fp32
__device__ float g_Q[MS*DM];
__device__ float g_K[MS*DM];
__device__ float g_V[MS*DM];
__device__ float g_T[MS*DM];
__device__ __nv_bfloat16 g_Xh[MS*DM];
__device__ __nv_bfloat16 g_Xl[MS*DM];
__device__ __nv_bfloat16 g_Th[MS*DM];
__device__ __nv_bfloat16 g_Tl[MS*DM];
__device__ __nv_bfloat16 g_Fh[(size_t)MS*DFF_];
__device__ __nv_bfloat16 g_Fl[(size_t)MS*DFF_];
// transposed+split weights: per layer [q,k,v,o: 1M each][w1T: 4M][w2T: 4M]
#define WL_ (12u*1024u*1024u)
__device__ __nv_bfloat16 g_Wh[(size_t)LNUM*WL_];
__device__ __nv_bfloat16 g_Wl[(size_t)LNUM*WL_];
// attention
#define NCH 8
__device__ float g_KVp[(size_t)NCH*BSZ*HH*DHD*DHD];
__device__ float g_KSp[NCH*BSZ*HH*DHD];
__device__ float g_KV[BSZ*HH*DHD*DHD];
__device__ float g_KS[BSZ*HH*DHD];

// ---------------------------------------------------------------------------
// PTX helpers (all sm_80-baseline: compile for compute_103)
// ---------------------------------------------------------------------------
__device__ __forceinline__ uint32_t smem_u32(const void* p) {
    uint32_t a;
    asm("{ .reg .u64 t; cvta.to.shared.u64 t, %1; cvt.u32.u64 %0, t; }"
        : "=r"(a) : "l"(p));
    return a;
}

#define CP_ASYNC16(s, g) \
    asm volatile("cp.async.cg.shared.global [%0], [%1], 16;" :: "r"(s), "l"(g))
#define CP_COMMIT()   asm volatile("cp.async.commit_group;")
#define CP_WAIT(n)    asm volatile("cp.async.wait_group %0;" :: "n"(n))

#define LDSM4(r0, r1, r2, r3, a) \
    asm volatile("ldmatrix.sync.aligned.m8n8.x4.shared.b16 {%0,%1,%2,%3}, [%4];" \
                 : "=r"(r0), "=r"(r1), "=r"(r2), "=r"(r3) : "r"(a))

#define MMA16816(d, a, b) \
    asm volatile("mma.sync.aligned.m16n8k16.row.col.f32.bf16.bf16.f32 " \
                 "{%0,%1,%2,%3}, {%4,%5,%6,%7}, {%8,%9}, {%0,%1,%2,%3};" \
                 : "+f"((d)[0]), "+f"((d)[1]), "+f"((d)[2]), "+f"((d)[3]) \
                 : "r"((a)[0]), "r"((a)[1]), "r"((a)[2]), "r"((a)[3]), \
                   "r"((b)[0]), "r"((b)[1]))

// swizzled smem address: rows of 64 B (4 x 16B chunks), chunk ^= (row>>1)&3
__device__ __forceinline__ uint32_t swz(uint32_t base, int row, int c) {
    return base + (row << 6) + (((c ^ ((row >> 1) & 3)) & 3) << 4);
}

__device__ __forceinline__ void split1(float v, __nv_bfloat16& h, __nv_bfloat16& l) {
    h = __float2bfloat16(v);
    l = __float2bfloat16(v - __bfloat162float(h));
}

// ---------------------------------------------------------------------------
// copy x -> g_X + split to g_Xh/g_Xl
// ---------------------------------------------------------------------------
__global__ void __launch_bounds__(256) copy_split_kernel(
    const float* __restrict__ src, float* __restrict__ dst,
    __nv_bfloat16* __restrict__ dh, __nv_bfloat16* __restrict__ dl)
{
    size_t i = ((size_t)blockIdx.x * 256 + threadIdx.x) * 4;
    float4 v = *(const float4*)(src + i);
    *(float4*)(dst + i) = v;
    alignas(8) __nv_bfloat16 hb[4], lb[4];
    split1(v.x, hb[0], lb[0]); split1(v.y, hb[1], lb[1]);
    split1(v.z, hb[2], lb[2]); split1(v.w, hb[3], lb[3]);
    *(uint2*)(dh + i) = *(uint2*)hb;
    *(uint2*)(dl + i) = *(uint2*)lb;
}

// ---------------------------------------------------------------------------
// weight transpose + split: W[K,N] fp32 -> Oh/Ol [N,K] bf16
// ---------------------------------------------------------------------------
__global__ void __launch_bounds__(256) tsplit_kernel(
    const float* __restrict__ W, __nv_bfloat16* __restrict__ Oh,
    __nv_bfloat16* __restrict__ Ol, int K, int N)
{
    __shared__ float t[32][33];
    const int k0 = blockIdx.y * 32, n0 = blockIdx.x * 32;
    const int tx = threadIdx.x, ty = threadIdx.y;    // 32 x 8
#pragma unroll
    for (int i = 0; i < 4; i++)
        t[ty + 8 * i][tx] = W[(size_t)(k0 + ty + 8 * i) * N + n0 + tx];
    __syncthreads();
#pragma unroll
    for (int i = 0; i < 4; i++) {
        const int n = n0 + ty + 8 * i;
        float v = t[tx][ty + 8 * i];
        __nv_bfloat16 h, l; split1(v, h, l);
        Oh[(size_t)n * K + k0 + tx] = h;
        Ol[(size_t)n * K + k0 + tx] = l;
    }
}

// ---------------------------------------------------------------------------
// bf16x3 GEMM via mma.sync: C[M,N] = act(A @ B^T + bias)
// A = Ah+Al [M,K] bf16 row-major; B = Bh+Bl [N,K] bf16 row-major
// ACT: 0 none, 1 elu+1, 2 relu.  OUT: 0 fp32 C, 1 split bf16 (Ch,Cl)
// 512 thr, warp grid 4(M)x4(N), warp tile 32x32, 3-stage cp.async pipeline.
// ---------------------------------------------------------------------------
template<int ACT, int OUT>
__global__ void __launch_bounds__(GT, 1) gemm_mma(
    const __nv_bfloat16* __restrict__ Ah, const __nv_bfloat16* __restrict__ Al,
    const __nv_bfloat16* __restrict__ Bh, const __nv_bfloat16* __restrict__ Bl,
    const float* __restrict__ bias,
    float* __restrict__ C, __nv_bfloat16* __restrict__ Ch, __nv_bfloat16* __restrict__ Cl,
    int M, int N, int K)
{
    extern __shared__ char smem[];
    const uint32_t sb = smem_u32(smem);
    const uint32_t sData = sb + BIAS_BYTES;
    const int tid  = threadIdx.x;
    const int wid  = tid >> 5;
    const int lane = tid & 31;
    const int wm   = wid & 3;          // M warp coord (tiles of 32)
    const int wn   = wid >> 2;         // N warp coord (tiles of 32)
    const int m0   = blockIdx.y * BM;
    const int n0   = blockIdx.x * BN;

    if (tid < 128) ((float*)smem)[tid] = bias[n0 + tid];

    const int NC = K >> 5;             // K / 32 chunks

    // ---- stage loader: 2048 x 16B chunks, 4 per thread ----
    auto load_stage = [&](int s, int c) {
        const uint32_t stg = sData + s * STG_BYTES;
        const int kc = c << 5;
#pragma unroll
        for (int it = 0; it < 4; it++) {
            const int id   = tid + it * GT;        // 0..2047
            const int part = id >> 9;              // 0:Ah 1:Al 2:Bh 3:Bl
            const int w    = id & 511;
            const int row  = w >> 2;
            const int cc   = w & 3;
            const __nv_bfloat16* g;
            uint32_t sa;
            if (part == 0)      { g = Ah + (size_t)(m0 + row) * K + kc + cc * 8; sa = swz(stg + OFF_AH, row, cc); }
            else if (part == 1) { g = Al + (size_t)(m0 + row) * K + kc + cc * 8; sa = swz(stg + OFF_AL, row, cc); }
            else if (part == 2) { g = Bh + (size_t)(n0 + row) * K + kc + cc * 8; sa = swz(stg + OFF_BH, row, cc); }
            else                { g = Bl + (size_t)(n0 + row) * K + kc + cc * 8; sa = swz(stg + OFF_BL, row, cc); }
            CP_ASYNC16(sa, g);
        }
    };

    load_stage(0, 0); CP_COMMIT();
    load_stage(1, 1); CP_COMMIT();

    float acc[2][4][4];
#pragma unroll
    for (int mt = 0; mt < 2; mt++)
#pragma unroll
        for (int j = 0; j < 4; j++)
#pragma unroll
            for (int q = 0; q < 4; q++) acc[mt][j][q] = 0.f;

    // precomputed fragment geometry
    const int arow = wm * 32 + (lane & 15);              // + mt*16
    const int acol = lane >> 4;                          // + kk*2
    const int brow = wn * 32 + ((lane >> 4) << 3) + (lane & 7);  // + nt*16
    const int bcol = (lane >> 3) & 1;                    // + kk*2

    for (int c = 0; c < NC; c++) {
        CP_WAIT(1);
        __syncthreads();
        if (c + 2 < NC) load_stage((c + 2) % NSTG, c + 2);
        CP_COMMIT();

        const uint32_t stg = sData + (c % NSTG) * STG_BYTES;
#pragma unroll
        for (int kk = 0; kk < 2; kk++) {
            const int kc8 = kk * 2;
            uint32_t ah[2][4], al[2][4], bh[4][2], bl[4][2];
#pragma unroll
            for (int mt = 0; mt < 2; mt++) {
                const int r = arow + mt * 16;
                const int cA = kc8 + acol;
                LDSM4(ah[mt][0], ah[mt][1], ah[mt][2], ah[mt][3], swz(stg + OFF_AH, r, cA));
                LDSM4(al[mt][0], al[mt][1], al[mt][2], al[mt][3], swz(stg + OFF_AL, r, cA));
            }
#pragma unroll
            for (int nt = 0; nt < 2; nt++) {
                const int r = brow + nt * 16;
                const int cB = kc8 + bcol;
                uint32_t t0, t1, t2, t3;
                LDSM4(t0, t1, t2, t3, swz(stg + OFF_BH, r, cB));
                bh[nt*2][0] = t0; bh[nt*2][1] = t1; bh[nt*2+1][0] = t2; bh[nt*2+1][1] = t3;
                LDSM4(t0, t1, t2, t3, swz(stg + OFF_BL, r, cB));
                bl[nt*2][0] = t0; bl[nt*2][1] = t1; bl[nt*2+1][0] = t2; bl[nt*2+1][1] = t3;
            }
#pragma unroll
            for (int mt = 0; mt < 2; mt++)
#pragma unroll
                for (int j = 0; j < 4; j++) {
                    MMA16816(acc[mt][j], ah[mt], bh[j]);
                    MMA16816(acc[mt][j], ah[mt], bl[j]);
                    MMA16816(acc[mt][j], al[mt], bh[j]);
                }
        }
    }

    // ---- epilogue: bias + act, write fp32 or split bf16 ----
    const float* bsm = (const float*)smem;
#pragma unroll
    for (int mt = 0; mt < 2; mt++) {
#pragma unroll
        for (int j = 0; j < 4; j++) {
            const int col = wn * 32 + j * 8 + (lane & 3) * 2;
            const float b0 = bsm[col], b1 = bsm[col + 1];
            const int gcol = n0 + col;
#pragma unroll
            for (int half = 0; half < 2; half++) {
                const int grow = m0 + wm * 32 + mt * 16 + (lane >> 2) + half * 8;
                float v0 = acc[mt][j][half * 2 + 0] + b0;
                float v1 = acc[mt][j][half * 2 + 1] + b1;
                if (ACT == 1) {
                    v0 = (v0 > 0.f) ? (v0 + 1.f) : __expf(v0);
                    v1 = (v1 > 0.f) ? (v1 + 1.f) : __expf(v1);
                }
                if (ACT == 2) { v0 = fmaxf(v0, 0.f); v1 = fmaxf(v1, 0.f); }
                if (OUT == 0) {
                    float2 o; o.x = v0; o.y = v1;
                    *(float2*)(C + (size_t)grow * N + gcol) = o;
                } else {
                    alignas(4) __nv_bfloat16 h2[2], l2[2];
                    split1(v0, h2[0], l2[0]);
                    split1(v1, h2[1], l2[1]);
                    *(uint32_t*)(Ch + (size_t)grow * N + gcol) = *(uint32_t*)h2;
                    *(uint32_t*)(Cl + (size_t)grow * N + gcol) = *(uint32_t*)l2;
                }
            }
        }
    }
}

// ---------------------------------------------------------------------------
// kv partial: grid (64, NCH). Each block: 256 s-rows of one (b,h).
// ---------------------------------------------------------------------------
__global__ void __launch_bounds__(256) kv_part_kernel(
    const float* __restrict__ Kx, const float* __restrict__ Vx,
    float* __restrict__ KVp, float* __restrict__ KSp)
{
    const int bh = blockIdx.x;
    const int ch = blockIdx.y;
    const int b = bh >> 4, h = bh & 15;
    const int sbeg = ch * (SSZ / NCH);
    const float* Kb = Kx + (size_t)b * SSZ * DM + h * DHD;
    const float* Vb = Vx + (size_t)b * SSZ * DM + h * DHD;

    __shared__ float ks[32][64];
    __shared__ float vs[32][64];

    const int tid = threadIdx.x;
    const int ty = tid >> 4, tx = tid & 15;

    float acc[4][4] = {};
    float ksum = 0.f;

    for (int s0 = sbeg; s0 < sbeg + SSZ / NCH; s0 += 32) {
#pragma unroll
        for (int j = 0; j < 2; j++) {
            int idx = tid + j * 256;
            int r = idx >> 4, c4 = (idx & 15) * 4;
            *(float4*)&ks[r][c4] = *(const float4*)(Kb + (size_t)(s0 + r) * DM + c4);
            *(float4*)&vs[r][c4] = *(const float4*)(Vb + (size_t)(s0 + r) * DM + c4);
        }
        __syncthreads();
#pragma unroll 8
        for (int s = 0; s < 32; s++) {
            float a[4], bv[4];
#pragma unroll
            for (int i = 0; i < 4; i++) a[i] = ks[s][ty * 4 + i];
#pragma unroll
            for (int j = 0; j < 4; j++) bv[j] = vs[s][tx * 4 + j];
#pragma unroll
            for (int i = 0; i < 4; i++)
#pragma unroll
                for (int j = 0; j < 4; j++)
                    acc[i][j] = fmaf(a[i], bv[j], acc[i][j]);
        }
        if (tid < 64) {
#pragma unroll 8
            for (int s = 0; s < 32; s++) ksum += ks[s][tid];
        }
        __syncthreads();
    }

    float* KVb = KVp + ((size_t)ch * 64 + bh) * DHD * DHD;
#pragma unroll
    for (int i = 0; i < 4; i++)
#pragma unroll
        for (int j = 0; j < 4; j++)
            KVb[(ty * 4 + i) * DHD + tx * 4 + j] = acc[i][j];
    if (tid < 64) KSp[(ch * 64 + bh) * DHD + tid] = ksum;
}

__global__ void __launch_bounds__(256) kv_final_kernel(
    const float* __restrict__ KVp, const float* __restrict__ KSp,
    float* __restrict__ KV, float* __restrict__ KS)
{
    const int bh = blockIdx.x;
    const int tid = threadIdx.x;
    float a[16] = {};
#pragma unroll
    for (int p = 0; p < NCH; p++) {
        const float* src = KVp + ((size_t)p * 64 + bh) * 4096 + tid * 16;
#pragma unroll
        for (int j = 0; j < 16; j++) a[j] += src[j];
    }
    float* dst = KV + (size_t)bh * 4096 + tid * 16;
#pragma unroll
    for (int j = 0; j < 16; j++) dst[j] = a[j];
    if (tid < 64) {
        float s = 0.f;
#pragma unroll
        for (int p = 0; p < NCH; p++) s += KSp[(p * 64 + bh) * DHD + tid];
        KS[bh * DHD + tid] = s;
    }
}

// ---------------------------------------------------------------------------
// attn out: o = z * (q @ kv); writes split bf16 (Th, Tl)
// ---------------------------------------------------------------------------
__global__ void __launch_bounds__(256) attn_out_kernel(
    const float* __restrict__ Qx, const float* __restrict__ KVi,
    const float* __restrict__ KSi,
    __nv_bfloat16* __restrict__ Oh, __nv_bfloat16* __restrict__ Ol)
{
    const int bh = blockIdx.x;
    const int b = bh >> 4, h = bh & 15;
    const int s0 = blockIdx.y * 64;

    __shared__ float qs[64][64];
    __shared__ float kvs[64][64];
    __shared__ float kss[64];

    const int tid = threadIdx.x;
    const float* Qb  = Qx + (size_t)(b * SSZ + s0) * DM + h * DHD;
    const float* KVb = KVi + (size_t)bh * DHD * DHD;

#pragma unroll
    for (int j = 0; j < 4; j++) {
        int idx = tid + j * 256;
        int r = idx >> 4, c4 = (idx & 15) * 4;
        *(float4*)&qs[r][c4]  = *(const float4*)(Qb + (size_t)r * DM + c4);
        *(float4*)&kvs[r][c4] = *(const float4*)(KVb + r * DHD + c4);
    }
    if (tid < 64) kss[tid] = KSi[bh * DHD + tid];
    __syncthreads();

    const int row = tid >> 2;
    const int mo  = (tid & 3) * 16;

    float z = 0.f;
#pragma unroll
    for (int d = 0; d < 64; d++) z = fmaf(qs[row][d], kss[d], z);
    z = 1.f / (z + 1e-6f);

    float acc[16] = {};
#pragma unroll
    for (int d = 0; d < 64; d++) {
        float qd = qs[row][d];
#pragma unroll
        for (int m = 0; m < 16; m++)
            acc[m] = fmaf(qd, kvs[d][mo + m], acc[m]);
    }

    alignas(16) __nv_bfloat16 hb[16], lb[16];
#pragma unroll
    for (int m = 0; m < 16; m++) split1(acc[m] * z, hb[m], lb[m]);
    const size_t base = (size_t)(b * SSZ + s0 + row) * DM + h * DHD + mo;
    *(uint4*)(Oh + base)     = ((uint4*)hb)[0];
    *(uint4*)(Oh + base + 8) = ((uint4*)hb)[1];
    *(uint4*)(Ol + base)     = ((uint4*)lb)[0];
    *(uint4*)(Ol + base + 8) = ((uint4*)lb)[1];
}

// ---------------------------------------------------------------------------
// LayerNorm(X (+ Y)); writes fp32 out and (optionally) split bf16 out
// ---------------------------------------------------------------------------
__global__ void __launch_bounds__(256) ln_kernel(
    const float* X, const float* Yr, const float* __restrict__ w,
    const float* __restrict__ bb, float* out,
    __nv_bfloat16* oh, __nv_bfloat16* ol, int has_res, int do_split)
{
    __shared__ float ss[8], ssq[8];
    __shared__ float sm, sr;

    const int row = blockIdx.x;
    const int tid = threadIdx.x;
    const int c = tid * 4;

    float4 xv = *(const float4*)(X + (size_t)row * DM + c);
    float v0 = xv.x, v1 = xv.y, v2 = xv.z, v3 = xv.w;
    if (has_res) {
        float4 yv = *(const float4*)(Yr + (size_t)row * DM + c);
        v0 += yv.x; v1 += yv.y; v2 += yv.z; v3 += yv.w;
    }

    float s  = v0 + v1 + v2 + v3;
    float sq = v0 * v0 + v1 * v1 + v2 * v2 + v3 * v3;
#pragma unroll
    for (int off = 16; off; off >>= 1) {
        s  += __shfl_xor_sync(0xffffffffu, s,  off);
        sq += __shfl_xor_sync(0xffffffffu, sq, off);
    }
    const int wid = tid >> 5, lane = tid & 31;
    if (lane == 0) { ss[wid] = s; ssq[wid] = sq; }
    __syncthreads();
    if (tid == 0) {
        float t = 0.f, tq = 0.f;
#pragma unroll
        for (int i = 0; i < 8; i++) { t += ss[i]; tq += ssq[i]; }
        float mean = t * (1.f / DM);
        float var  = tq * (1.f / DM) - mean * mean;
        sm = mean;
        sr = rsqrtf(var + 1e-5f);
    }
    __syncthreads();
    const float mean = sm, rstd = sr;

    float4 wv = *(const float4*)(w + c);
    float4 bv = *(const float4*)(bb + c);
    float4 ov;
    ov.x = (v0 - mean) * rstd * wv.x + bv.x;
    ov.y = (v1 - mean) * rstd * wv.y + bv.y;
    ov.z = (v2 - mean) * rstd * wv.z + bv.z;
    ov.w = (v3 - mean) * rstd * wv.w + bv.w;
    *(float4*)(out + (size_t)row * DM + c) = ov;

    if (do_split) {
        alignas(8) __nv_bfloat16 hb[4], lb[4];
        split1(ov.x, hb[0], lb[0]); split1(ov.y, hb[1], lb[1]);
        split1(ov.z, hb[2], lb[2]); split1(ov.w, hb[3], lb[3]);
        *(uint2*)(oh + (size_t)row * DM + c) = *(uint2*)hb;
        *(uint2*)(ol + (size_t)row * DM + c) = *(uint2*)lb;
    }
}

// ---------------------------------------------------------------------------
// Orchestration
// ---------------------------------------------------------------------------
extern "C" void kernel_launch(void* const* d_in, const int* in_sizes, int n_in,
                              void* d_out, int out_size)
{
    const float* x    = (const float*)d_in[0];
    const float* Wq   = (const float*)d_in[1];
    const float* bq   = (const float*)d_in[2];
    const float* Wk   = (const float*)d_in[3];
    const float* bk   = (const float*)d_in[4];
    const float* Wv   = (const float*)d_in[5];
    const float* bv   = (const float*)d_in[6];
    const float* Wo   = (const float*)d_in[7];
    const float* bo   = (const float*)d_in[8];
    const float* ln1w = (const float*)d_in[9];
    const float* ln1b = (const float*)d_in[10];
    const float* W1   = (const float*)d_in[11];
    const float* b1   = (const float*)d_in[12];
    const float* W2   = (const float*)d_in[13];
    const float* b2   = (const float*)d_in[14];
    const float* ln2w = (const float*)d_in[15];
    const float* ln2b = (const float*)d_in[16];
    const float* lnfw = (const float*)d_in[17];
    const float* lnfb = (const float*)d_in[18];

    float *X, *Q, *Kf, *Vf, *T, *KVp, *KSp, *KV, *KS;
    __nv_bfloat16 *Xh, *Xl, *Th, *Tl, *Fh, *Fl, *Wh, *Wl;
    cudaGetSymbolAddress((void**)&X,   g_X);
    cudaGetSymbolAddress((void**)&Q,   g_Q);
    cudaGetSymbolAddress((void**)&Kf,  g_K);
    cudaGetSymbolAddress((void**)&Vf,  g_V);
    cudaGetSymbolAddress((void**)&T,   g_T);
    cudaGetSymbolAddress((void**)&Xh,  g_Xh);
    cudaGetSymbolAddress((void**)&Xl,  g_Xl);
    cudaGetSymbolAddress((void**)&Th,  g_Th);
    cudaGetSymbolAddress((void**)&Tl,  g_Tl);
    cudaGetSymbolAddress((void**)&Fh,  g_Fh);
    cudaGetSymbolAddress((void**)&Fl,  g_Fl);
    cudaGetSymbolAddress((void**)&Wh,  g_Wh);
    cudaGetSymbolAddress((void**)&Wl,  g_Wl);
    cudaGetSymbolAddress((void**)&KVp, g_KVp);
    cudaGetSymbolAddress((void**)&KSp, g_KSp);
    cudaGetSymbolAddress((void**)&KV,  g_KV);
    cudaGetSymbolAddress((void**)&KS,  g_KS);

    cudaFuncSetAttribute(gemm_mma<1,0>, cudaFuncAttributeMaxDynamicSharedMemorySize, SMEM_G);
    cudaFuncSetAttribute(gemm_mma<0,0>, cudaFuncAttributeMaxDynamicSharedMemorySize, SMEM_G);
    cudaFuncSetAttribute(gemm_mma<2,1>, cudaFuncAttributeMaxDynamicSharedMemorySize, SMEM_G);

    // ---- weight transpose + split (all layers) ----
    const dim3 tb(32, 8);
    for (int l = 0; l < LNUM; l++) {
        size_t base = (size_t)l * WL_;
        const size_t M1 = (size_t)DM * DM;
        tsplit_kernel<<<dim3(DM/32, DM/32),  tb>>>(Wq + l*M1, Wh + base,        Wl + base,        DM,  DM);
        tsplit_kernel<<<dim3(DM/32, DM/32),  tb>>>(Wk + l*M1, Wh + base + M1,   Wl + base + M1,   DM,  DM);
        tsplit_kernel<<<dim3(DM/32, DM/32),  tb>>>(Wv + l*M1, Wh + base + 2*M1, Wl + base + 2*M1, DM,  DM);
        tsplit_kernel<<<dim3(DM/32, DM/32),  tb>>>(Wo + l*M1, Wh + base + 3*M1, Wl + base + 3*M1, DM,  DM);
        tsplit_kernel<<<dim3(DFF_/32, DM/32), tb>>>(W1 + (size_t)l*DM*DFF_, Wh + base + 4*M1, Wl + base + 4*M1, DM,  DFF_);
        tsplit_kernel<<<dim3(DM/32, DFF_/32), tb>>>(W2 + (size_t)l*DFF_*DM, Wh + base + 8*M1, Wl + base + 8*M1, DFF_, DM);
    }

    copy_split_kernel<<<(MS * DM) / 1024, 256>>>(x, X, Xh, Xl);

    const dim3 gD(DM / BN, MS / BM);      // (8, 64)
    const dim3 gF1(DFF_ / BN, MS / BM);   // (32, 64)

    for (int l = 0; l < LNUM; l++) {
        const size_t base = (size_t)l * WL_;
        const size_t M1 = (size_t)DM * DM;
        const __nv_bfloat16 *wqh = Wh + base,        *wql = Wl + base;
        const __nv_bfloat16 *wkh = Wh + base + M1,   *wkl = Wl + base + M1;
        const __nv_bfloat16 *wvh = Wh + base + 2*M1, *wvl = Wl + base + 2*M1;
        const __nv_bfloat16 *woh = Wh + base + 3*M1, *wol = Wl + base + 3*M1;
        const __nv_bfloat16 *w1h = Wh + base + 4*M1, *w1l = Wl + base + 4*M1;
        const __nv_bfloat16 *w2h = Wh + base + 8*M1, *w2l = Wl + base + 8*M1;
        const float* bqL = bq + (size_t)l * DM;
        const float* bkL = bk + (size_t)l * DM;
        const float* bvL = bv + (size_t)l * DM;
        const float* boL = bo + (size_t)l * DM;
        const float* b1L = b1 + (size_t)l * DFF_;
        const float* b2L = b2 + (size_t)l * DM;

        // Q = phi(X Wq + bq), K = phi(X Wk + bk), V = X Wv + bv
        gemm_mma<1,0><<<gD, GT, SMEM_G>>>(Xh, Xl, wqh, wql, bqL, Q,  0, 0, MS, DM, DM);
        gemm_mma<1,0><<<gD, GT, SMEM_G>>>(Xh, Xl, wkh, wkl, bkL, Kf, 0, 0, MS, DM, DM);
        gemm_mma<0,0><<<gD, GT, SMEM_G>>>(Xh, Xl, wvh, wvl, bvL, Vf, 0, 0, MS, DM, DM);

        // kv / ksum (2-stage deterministic reduce)
        kv_part_kernel<<<dim3(BSZ * HH, NCH), 256>>>(Kf, Vf, KVp, KSp);
        kv_final_kernel<<<BSZ * HH, 256>>>(KVp, KSp, KV, KS);

        // attn out (pre-projection), split bf16 -> (Th, Tl)
        attn_out_kernel<<<dim3(BSZ * HH, SSZ / 64), 256>>>(Q, KV, KS, Th, Tl);

        // projection -> Vf (fp32), then X = LN1(X + Vf), split -> (Xh, Xl)
        gemm_mma<0,0><<<gD, GT, SMEM_G>>>(Th, Tl, woh, wol, boL, Vf, 0, 0, MS, DM, DM);
        ln_kernel<<<MS, 256>>>(X, Vf, ln1w + (size_t)l*DM, ln1b + (size_t)l*DM, X, Xh, Xl, 1, 1);

        // FFN: (Fh,Fl) = split(relu(X W1 + b1)); T = F W2 + b2; X = LN2(X + T)
        gemm_mma<2,1><<<gF1, GT, SMEM_G>>>(Xh, Xl, w1h, w1l, b1L, 0, Fh, Fl, MS, DFF_, DM);
        gemm_mma<0,0><<<gD,  GT, SMEM_G>>>(Fh, Fl, w2h, w2l, b2L, T, 0, 0,  MS, DM, DFF_);
        ln_kernel<<<MS, 256>>>(X, T, ln2w + (size_t)l*DM, ln2b + (size_t)l*DM, X, Xh, Xl, 1, 1);
    }

    // final LayerNorm -> d_out (fp32, no split)
    ln_kernel<<<MS, 256>>>(X, X, lnfw, lnfb, (float*)d_out, 0, 0, 0, 0);
}

// round 16
// speedup vs baseline: 2.6064x; 1.0320x over previous
#include <cuda_runtime.h>
#include <cuda_bf16.h>
#include <math.h>
#include <stdint.h>

// Problem constants
#define BSZ   4
#define SSZ   2048
#define DM    1024
#define HH    16
#define DHD   64
#define DFF_  4096
#define LNUM  6
#define MS    (BSZ*SSZ)   // 8192 rows

// GEMM tiling (mma.sync path; tcgen05 not available via compute_103 toolchain)
#define BM 128
#define BN 128
#define BK 32
#define GT 256                 // 8 warps, warp grid 2(M) x 4(N), warp tile 64x32
#define NSTG 4
#define STG_BYTES 32768        // Ah/Al/Bh/Bl: 4 x 8192 B
#define OFF_AH 0
#define OFF_AL 8192
#define OFF_BH 16384
#define OFF_BL 24576
#define BIAS_BYTES 512
#define SMEM_G (BIAS_BYTES + NSTG*STG_BYTES)   // 131584 B

// ---------------------------------------------------------------------------
// Scratch (device globals — no allocation allowed)
// ---------------------------------------------------------------------------
__device__ float g_X[MS*DM];                 // residual stream fp32
__device__ float g_Q[MS*DM];
__device__ float g_K[MS*DM];
__device__ float g_V[MS*DM];
__device__ float g_T[MS*DM];
__device__ __nv_bfloat16 g_Xh[MS*DM];
__device__ __nv_bfloat16 g_Xl[MS*DM];
__device__ __nv_bfloat16 g_Th[MS*DM];
__device__ __nv_bfloat16 g_Tl[MS*DM];
__device__ __nv_bfloat16 g_Fh[(size_t)MS*DFF_];
__device__ __nv_bfloat16 g_Fl[(size_t)MS*DFF_];
// transposed+split weights: per layer [q,k,v,o: 1M each][w1T: 4M][w2T: 4M]
#define WL_ (12u*1024u*1024u)
__device__ __nv_bfloat16 g_Wh[(size_t)LNUM*WL_];
__device__ __nv_bfloat16 g_Wl[(size_t)LNUM*WL_];
// attention
#define NCH 8
__device__ float g_KVp[(size_t)NCH*BSZ*HH*DHD*DHD];
__device__ float g_KSp[NCH*BSZ*HH*DHD];
__device__ float g_KV[BSZ*HH*DHD*DHD];
__device__ float g_KS[BSZ*HH*DHD];

// ---------------------------------------------------------------------------
// PTX helpers (sm_80-baseline: compile for compute_103)
// ---------------------------------------------------------------------------
__device__ __forceinline__ uint32_t smem_u32(const void* p) {
    uint32_t a;
    asm("{ .reg .u64 t; cvta.to.shared.u64 t, %1; cvt.u32.u64 %0, t; }"
        : "=r"(a) : "l"(p));
    return a;
}

#define CP_ASYNC16(s, g) \
    asm volatile("cp.async.cg.shared.global [%0], [%1], 16;" :: "r"(s), "l"(g))
#define CP_COMMIT()   asm volatile("cp.async.commit_group;")
#define CP_WAIT(n)    asm volatile("cp.async.wait_group %0;" :: "n"(n))

#define LDSM4(r0, r1, r2, r3, a) \
    asm volatile("ldmatrix.sync.aligned.m8n8.x4.shared.b16 {%0,%1,%2,%3}, [%4];" \
                 : "=r"(r0), "=r"(r1), "=r"(r2), "=r"(r3) : "r"(a))

#define MMA16816(d, a, b) \
    asm volatile("mma.sync.aligned.m16n8k16.row.col.f32.bf16.bf16.f32 " \
                 "{%0,%1,%2,%3}, {%4,%5,%6,%7}, {%8,%9}, {%0,%1,%2,%3};" \
                 : "+f"((d)[0]), "+f"((d)[1]), "+f"((d)[2]), "+f"((d)[3]) \
                 : "r"((a)[0]), "r"((a)[1]), "r"((a)[2]), "r"((a)[3]), \
                   "r"((b)[0]), "r"((b)[1]))

// swizzled smem address: rows of 64 B (4 x 16B chunks), chunk ^= (row>>1)&3
// -> conflict-free for both cp.async stores and ldmatrix reads (verified R15)
__device__ __forceinline__ uint32_t swz(uint32_t base, int row, int c) {
    return base + (row << 6) + (((c ^ ((row >> 1) & 3)) & 3) << 4);
}

__device__ __forceinline__ void split1(float v, __nv_bfloat16& h, __nv_bfloat16& l) {
    h = __float2bfloat16(v);
    l = __float2bfloat16(v - __bfloat162float(h));
}

// ---------------------------------------------------------------------------
// copy x -> g_X + split to g_Xh/g_Xl
// ---------------------------------------------------------------------------
__global__ void __launch_bounds__(256) copy_split_kernel(
    const float* __restrict__ src, float* __restrict__ dst,
    __nv_bfloat16* __restrict__ dh, __nv_bfloat16* __restrict__ dl)
{
    size_t i = ((size_t)blockIdx.x * 256 + threadIdx.x) * 4;
    float4 v = *(const float4*)(src + i);
    *(float4*)(dst + i) = v;
    alignas(8) __nv_bfloat16 hb[4], lb[4];
    split1(v.x, hb[0], lb[0]); split1(v.y, hb[1], lb[1]);
    split1(v.z, hb[2], lb[2]); split1(v.w, hb[3], lb[3]);
    *(uint2*)(dh + i) = *(uint2*)hb;
    *(uint2*)(dl + i) = *(uint2*)lb;
}

// ---------------------------------------------------------------------------
// weight transpose + split: W[K,N] fp32 -> Oh/Ol [N,K] bf16
// ---------------------------------------------------------------------------
__global__ void __launch_bounds__(256) tsplit_kernel(
    const float* __restrict__ W, __nv_bfloat16* __restrict__ Oh,
    __nv_bfloat16* __restrict__ Ol, int K, int N)
{
    __shared__ float t[32][33];
    const int k0 = blockIdx.y * 32, n0 = blockIdx.x * 32;
    const int tx = threadIdx.x, ty = threadIdx.y;    // 32 x 8
#pragma unroll
    for (int i = 0; i < 4; i++)
        t[ty + 8 * i][tx] = W[(size_t)(k0 + ty + 8 * i) * N + n0 + tx];
    __syncthreads();
#pragma unroll
    for (int i = 0; i < 4; i++) {
        const int n = n0 + ty + 8 * i;
        float v = t[tx][ty + 8 * i];
        __nv_bfloat16 h, l; split1(v, h, l);
        Oh[(size_t)n * K + k0 + tx] = h;
        Ol[(size_t)n * K + k0 + tx] = l;
    }
}

// ---------------------------------------------------------------------------
// bf16x3 GEMM via mma.sync: C[M,N] = act(A @ B^T + bias)
// A = Ah+Al [M,K] bf16 row-major; B = Bh+Bl [N,K] bf16 row-major
// ACT: 0 none, 1 elu+1, 2 relu.  OUT: 0 fp32 C, 1 split bf16 (Ch,Cl)
// 256 thr, warp grid 2(M)x4(N), warp tile 64x32, 4-stage cp.async pipeline.
// ---------------------------------------------------------------------------
template<int ACT, int OUT>
__global__ void __launch_bounds__(GT, 1) gemm_mma(
    const __nv_bfloat16* __restrict__ Ah, const __nv_bfloat16* __restrict__ Al,
    const __nv_bfloat16* __restrict__ Bh, const __nv_bfloat16* __restrict__ Bl,
    const float* __restrict__ bias,
    float* __restrict__ C, __nv_bfloat16* __restrict__ Ch, __nv_bfloat16* __restrict__ Cl,
    int M, int N, int K)
{
    extern __shared__ char smem[];
    const uint32_t sb = smem_u32(smem);
    const uint32_t sData = sb + BIAS_BYTES;
    const int tid  = threadIdx.x;
    const int wid  = tid >> 5;
    const int lane = tid & 31;
    const int wm   = wid & 1;          // M warp coord (tiles of 64)
    const int wn   = wid >> 1;         // N warp coord (tiles of 32)
    const int m0   = blockIdx.y * BM;
    const int n0   = blockIdx.x * BN;

    if (tid < 128) ((float*)smem)[tid] = bias[n0 + tid];

    const int NC = K >> 5;             // K / 32 chunks

    // ---- stage loader: 2048 x 16B chunks, 8 per thread ----
    auto load_stage = [&](int s, int c) {
        const uint32_t stg = sData + s * STG_BYTES;
        const int kc = c << 5;
#pragma unroll
        for (int it = 0; it < 8; it++) {
            const int id   = tid + it * GT;        // 0..2047
            const int part = id >> 9;              // 0:Ah 1:Al 2:Bh 3:Bl
            const int w    = id & 511;
            const int row  = w >> 2;
            const int cc   = w & 3;
            const __nv_bfloat16* g;
            uint32_t sa;
            if (part == 0)      { g = Ah + (size_t)(m0 + row) * K + kc + cc * 8; sa = swz(stg + OFF_AH, row, cc); }
            else if (part == 1) { g = Al + (size_t)(m0 + row) * K + kc + cc * 8; sa = swz(stg + OFF_AL, row, cc); }
            else if (part == 2) { g = Bh + (size_t)(n0 + row) * K + kc + cc * 8; sa = swz(stg + OFF_BH, row, cc); }
            else                { g = Bl + (size_t)(n0 + row) * K + kc + cc * 8; sa = swz(stg + OFF_BL, row, cc); }
            CP_ASYNC16(sa, g);
        }
    };

    load_stage(0, 0); CP_COMMIT();
    load_stage(1, 1); CP_COMMIT();
    load_stage(2, 2); CP_COMMIT();

    float acc[4][4][4];
#pragma unroll
    for (int mt = 0; mt < 4; mt++)
#pragma unroll
        for (int j = 0; j < 4; j++)
#pragma unroll
            for (int q = 0; q < 4; q++) acc[mt][j][q] = 0.f;

    // fragment geometry
    const int arow = wm * 64 + (lane & 15);              // + mt*16
    const int acol = lane >> 4;                          // + kk*2
    const int brow = wn * 32 + ((lane >> 4) << 3) + (lane & 7);  // + nt*16
    const int bcol = (lane >> 3) & 1;                    // + kk*2

    for (int c = 0; c < NC; c++) {
        CP_WAIT(2);
        __syncthreads();
        if (c + 3 < NC) load_stage((c + 3) & 3, c + 3);
        CP_COMMIT();

        const uint32_t stg = sData + (c & 3) * STG_BYTES;
#pragma unroll
        for (int kk = 0; kk < 2; kk++) {
            const int kc8 = kk * 2;
            uint32_t ah[4][4], al[4][4], bh[4][2], bl[4][2];
#pragma unroll
            for (int mt = 0; mt < 4; mt++) {
                const int r = arow + mt * 16;
                const int cA = kc8 + acol;
                LDSM4(ah[mt][0], ah[mt][1], ah[mt][2], ah[mt][3], swz(stg + OFF_AH, r, cA));
                LDSM4(al[mt][0], al[mt][1], al[mt][2], al[mt][3], swz(stg + OFF_AL, r, cA));
            }
#pragma unroll
            for (int nt = 0; nt < 2; nt++) {
                const int r = brow + nt * 16;
                const int cB = kc8 + bcol;
                uint32_t t0, t1, t2, t3;
                LDSM4(t0, t1, t2, t3, swz(stg + OFF_BH, r, cB));
                bh[nt*2][0] = t0; bh[nt*2][1] = t1; bh[nt*2+1][0] = t2; bh[nt*2+1][1] = t3;
                LDSM4(t0, t1, t2, t3, swz(stg + OFF_BL, r, cB));
                bl[nt*2][0] = t0; bl[nt*2][1] = t1; bl[nt*2+1][0] = t2; bl[nt*2+1][1] = t3;
            }
            // three split-term sweeps; dependent MMAs on one acc are 16 apart
#pragma unroll
            for (int mt = 0; mt < 4; mt++)
#pragma unroll
                for (int j = 0; j < 4; j++)
                    MMA16816(acc[mt][j], ah[mt], bh[j]);
#pragma unroll
            for (int mt = 0; mt < 4; mt++)
#pragma unroll
                for (int j = 0; j < 4; j++)
                    MMA16816(acc[mt][j], ah[mt], bl[j]);
#pragma unroll
            for (int mt = 0; mt < 4; mt++)
#pragma unroll
                for (int j = 0; j < 4; j++)
                    MMA16816(acc[mt][j], al[mt], bh[j]);
        }
    }

    // ---- epilogue: bias + act, write fp32 or split bf16 ----
    const float* bsm = (const float*)smem;
#pragma unroll
    for (int mt = 0; mt < 4; mt++) {
#pragma unroll
        for (int j = 0; j < 4; j++) {
            const int col = wn * 32 + j * 8 + (lane & 3) * 2;
            const float b0 = bsm[col], b1 = bsm[col + 1];
            const int gcol = n0 + col;
#pragma unroll
            for (int half = 0; half < 2; half++) {
                const int grow = m0 + wm * 64 + mt * 16 + (lane >> 2) + half * 8;
                float v0 = acc[mt][j][half * 2 + 0] + b0;
                float v1 = acc[mt][j][half * 2 + 1] + b1;
                if (ACT == 1) {
                    v0 = (v0 > 0.f) ? (v0 + 1.f) : __expf(v0);
                    v1 = (v1 > 0.f) ? (v1 + 1.f) : __expf(v1);
                }
                if (ACT == 2) { v0 = fmaxf(v0, 0.f); v1 = fmaxf(v1, 0.f); }
                if (OUT == 0) {
                    float2 o; o.x = v0; o.y = v1;
                    *(float2*)(C + (size_t)grow * N + gcol) = o;
                } else {
                    alignas(4) __nv_bfloat16 h2[2], l2[2];
                    split1(v0, h2[0], l2[0]);
                    split1(v1, h2[1], l2[1]);
                    *(uint32_t*)(Ch + (size_t)grow * N + gcol) = *(uint32_t*)h2;
                    *(uint32_t*)(Cl + (size_t)grow * N + gcol) = *(uint32_t*)l2;
                }
            }
        }
    }
}

// ---------------------------------------------------------------------------
// kv partial: grid (64, NCH). Each block: 256 s-rows of one (b,h).
// ---------------------------------------------------------------------------
__global__ void __launch_bounds__(256) kv_part_kernel(
    const float* __restrict__ Kx, const float* __restrict__ Vx,
    float* __restrict__ KVp, float* __restrict__ KSp)
{
    const int bh = blockIdx.x;
    const int ch = blockIdx.y;
    const int b = bh >> 4, h = bh & 15;
    const int sbeg = ch * (SSZ / NCH);
    const float* Kb = Kx + (size_t)b * SSZ * DM + h * DHD;
    const float* Vb = Vx + (size_t)b * SSZ * DM + h * DHD;

    __shared__ float ks[32][64];
    __shared__ float vs[32][64];

    const int tid = threadIdx.x;
    const int ty = tid >> 4, tx = tid & 15;

    float acc[4][4] = {};
    float ksum = 0.f;

    for (int s0 = sbeg; s0 < sbeg + SSZ / NCH; s0 += 32) {
#pragma unroll
        for (int j = 0; j < 2; j++) {
            int idx = tid + j * 256;
            int r = idx >> 4, c4 = (idx & 15) * 4;
            *(float4*)&ks[r][c4] = *(const float4*)(Kb + (size_t)(s0 + r) * DM + c4);
            *(float4*)&vs[r][c4] = *(const float4*)(Vb + (size_t)(s0 + r) * DM + c4);
        }
        __syncthreads();
#pragma unroll 8
        for (int s = 0; s < 32; s++) {
            float a[4], bv[4];
#pragma unroll
            for (int i = 0; i < 4; i++) a[i] = ks[s][ty * 4 + i];
#pragma unroll
            for (int j = 0; j < 4; j++) bv[j] = vs[s][tx * 4 + j];
#pragma unroll
            for (int i = 0; i < 4; i++)
#pragma unroll
                for (int j = 0; j < 4; j++)
                    acc[i][j] = fmaf(a[i], bv[j], acc[i][j]);
        }
        if (tid < 64) {
#pragma unroll 8
            for (int s = 0; s < 32; s++) ksum += ks[s][tid];
        }
        __syncthreads();
    }

    float* KVb = KVp + ((size_t)ch * 64 + bh) * DHD * DHD;
#pragma unroll
    for (int i = 0; i < 4; i++)
#pragma unroll
        for (int j = 0; j < 4; j++)
            KVb[(ty * 4 + i) * DHD + tx * 4 + j] = acc[i][j];
    if (tid < 64) KSp[(ch * 64 + bh) * DHD + tid] = ksum;
}

__global__ void __launch_bounds__(256) kv_final_kernel(
    const float* __restrict__ KVp, const float* __restrict__ KSp,
    float* __restrict__ KV, float* __restrict__ KS)
{
    const int bh = blockIdx.x;
    const int tid = threadIdx.x;
    float a[16] = {};
#pragma unroll
    for (int p = 0; p < NCH; p++) {
        const float* src = KVp + ((size_t)p * 64 + bh) * 4096 + tid * 16;
#pragma unroll
        for (int j = 0; j < 16; j++) a[j] += src[j];
    }
    float* dst = KV + (size_t)bh * 4096 + tid * 16;
#pragma unroll
    for (int j = 0; j < 16; j++) dst[j] = a[j];
    if (tid < 64) {
        float s = 0.f;
#pragma unroll
        for (int p = 0; p < NCH; p++) s += KSp[(p * 64 + bh) * DHD + tid];
        KS[bh * DHD + tid] = s;
    }
}

// ---------------------------------------------------------------------------
// attn out: o = z * (q @ kv); writes split bf16 (Th, Tl)
// ---------------------------------------------------------------------------
__global__ void __launch_bounds__(256) attn_out_kernel(
    const float* __restrict__ Qx, const float* __restrict__ KVi,
    const float* __restrict__ KSi,
    __nv_bfloat16* __restrict__ Oh, __nv_bfloat16* __restrict__ Ol)
{
    const int bh = blockIdx.x;
    const int b = bh >> 4, h = bh & 15;
    const int s0 = blockIdx.y * 64;

    __shared__ float qs[64][64];
    __shared__ float kvs[64][64];
    __shared__ float kss[64];

    const int tid = threadIdx.x;
    const float* Qb  = Qx + (size_t)(b * SSZ + s0) * DM + h * DHD;
    const float* KVb = KVi + (size_t)bh * DHD * DHD;

#pragma unroll
    for (int j = 0; j < 4; j++) {
        int idx = tid + j * 256;
        int r = idx >> 4, c4 = (idx & 15) * 4;
        *(float4*)&qs[r][c4]  = *(const float4*)(Qb + (size_t)r * DM + c4);
        *(float4*)&kvs[r][c4] = *(const float4*)(KVb + r * DHD + c4);
    }
    if (tid < 64) kss[tid] = KSi[bh * DHD + tid];
    __syncthreads();

    const int row = tid >> 2;
    const int mo  = (tid & 3) * 16;

    float z = 0.f;
#pragma unroll
    for (int d = 0; d < 64; d++) z = fmaf(qs[row][d], kss[d], z);
    z = 1.f / (z + 1e-6f);

    float acc[16] = {};
#pragma unroll
    for (int d = 0; d < 64; d++) {
        float qd = qs[row][d];
#pragma unroll
        for (int m = 0; m < 16; m++)
            acc[m] = fmaf(qd, kvs[d][mo + m], acc[m]);
    }

    alignas(16) __nv_bfloat16 hb[16], lb[16];
#pragma unroll
    for (int m = 0; m < 16; m++) split1(acc[m] * z, hb[m], lb[m]);
    const size_t base = (size_t)(b * SSZ + s0 + row) * DM + h * DHD + mo;
    *(uint4*)(Oh + base)     = ((uint4*)hb)[0];
    *(uint4*)(Oh + base + 8) = ((uint4*)hb)[1];
    *(uint4*)(Ol + base)     = ((uint4*)lb)[0];
    *(uint4*)(Ol + base + 8) = ((uint4*)lb)[1];
}

// ---------------------------------------------------------------------------
// LayerNorm(X (+ Y)); writes fp32 out and (optionally) split bf16 out
// ---------------------------------------------------------------------------
__global__ void __launch_bounds__(256) ln_kernel(
    const float* X, const float* Yr, const float* __restrict__ w,
    const float* __restrict__ bb, float* out,
    __nv_bfloat16* oh, __nv_bfloat16* ol, int has_res, int do_split)
{
    __shared__ float ss[8], ssq[8];
    __shared__ float sm, sr;

    const int row = blockIdx.x;
    const int tid = threadIdx.x;
    const int c = tid * 4;

    float4 xv = *(const float4*)(X + (size_t)row * DM + c);
    float v0 = xv.x, v1 = xv.y, v2 = xv.z, v3 = xv.w;
    if (has_res) {
        float4 yv = *(const float4*)(Yr + (size_t)row * DM + c);
        v0 += yv.x; v1 += yv.y; v2 += yv.z; v3 += yv.w;
    }

    float s  = v0 + v1 + v2 + v3;
    float sq = v0 * v0 + v1 * v1 + v2 * v2 + v3 * v3;
#pragma unroll
    for (int off = 16; off; off >>= 1) {
        s  += __shfl_xor_sync(0xffffffffu, s,  off);
        sq += __shfl_xor_sync(0xffffffffu, sq, off);
    }
    const int wid = tid >> 5, lane = tid & 31;
    if (lane == 0) { ss[wid] = s; ssq[wid] = sq; }
    __syncthreads();
    if (tid == 0) {
        float t = 0.f, tq = 0.f;
#pragma unroll
        for (int i = 0; i < 8; i++) { t += ss[i]; tq += ssq[i]; }
        float mean = t * (1.f / DM);
        float var  = tq * (1.f / DM) - mean * mean;
        sm = mean;
        sr = rsqrtf(var + 1e-5f);
    }
    __syncthreads();
    const float mean = sm, rstd = sr;

    float4 wv = *(const float4*)(w + c);
    float4 bv = *(const float4*)(bb + c);
    float4 ov;
    ov.x = (v0 - mean) * rstd * wv.x + bv.x;
    ov.y = (v1 - mean) * rstd * wv.y + bv.y;
    ov.z = (v2 - mean) * rstd * wv.z + bv.z;
    ov.w = (v3 - mean) * rstd * wv.w + bv.w;
    *(float4*)(out + (size_t)row * DM + c) = ov;

    if (do_split) {
        alignas(8) __nv_bfloat16 hb[4], lb[4];
        split1(ov.x, hb[0], lb[0]); split1(ov.y, hb[1], lb[1]);
        split1(ov.z, hb[2], lb[2]); split1(ov.w, hb[3], lb[3]);
        *(uint2*)(oh + (size_t)row * DM + c) = *(uint2*)hb;
        *(uint2*)(ol + (size_t)row * DM + c) = *(uint2*)lb;
    }
}

// ---------------------------------------------------------------------------
// Orchestration
// ---------------------------------------------------------------------------
extern "C" void kernel_launch(void* const* d_in, const int* in_sizes, int n_in,
                              void* d_out, int out_size)
{
    const float* x    = (const float*)d_in[0];
    const float* Wq   = (const float*)d_in[1];
    const float* bq   = (const float*)d_in[2];
    const float* Wk   = (const float*)d_in[3];
    const float* bk   = (const float*)d_in[4];
    const float* Wv   = (const float*)d_in[5];
    const float* bv   = (const float*)d_in[6];
    const float* Wo   = (const float*)d_in[7];
    const float* bo   = (const float*)d_in[8];
    const float* ln1w = (const float*)d_in[9];
    const float* ln1b = (const float*)d_in[10];
    const float* W1   = (const float*)d_in[11];
    const float* b1   = (const float*)d_in[12];
    const float* W2   = (const float*)d_in[13];
    const float* b2   = (const float*)d_in[14];
    const float* ln2w = (const float*)d_in[15];
    const float* ln2b = (const float*)d_in[16];
    const float* lnfw = (const float*)d_in[17];
    const float* lnfb = (const float*)d_in[18];

    float *X, *Q, *Kf, *Vf, *T, *KVp, *KSp, *KV, *KS;
    __nv_bfloat16 *Xh, *Xl, *Th, *Tl, *Fh, *Fl, *Wh, *Wl;
    cudaGetSymbolAddress((void**)&X,   g_X);
    cudaGetSymbolAddress((void**)&Q,   g_Q);
    cudaGetSymbolAddress((void**)&Kf,  g_K);
    cudaGetSymbolAddress((void**)&Vf,  g_V);
    cudaGetSymbolAddress((void**)&T,   g_T);
    cudaGetSymbolAddress((void**)&Xh,  g_Xh);
    cudaGetSymbolAddress((void**)&Xl,  g_Xl);
    cudaGetSymbolAddress((void**)&Th,  g_Th);
    cudaGetSymbolAddress((void**)&Tl,  g_Tl);
    cudaGetSymbolAddress((void**)&Fh,  g_Fh);
    cudaGetSymbolAddress((void**)&Fl,  g_Fl);
    cudaGetSymbolAddress((void**)&Wh,  g_Wh);
    cudaGetSymbolAddress((void**)&Wl,  g_Wl);
    cudaGetSymbolAddress((void**)&KVp, g_KVp);
    cudaGetSymbolAddress((void**)&KSp, g_KSp);
    cudaGetSymbolAddress((void**)&KV,  g_KV);
    cudaGetSymbolAddress((void**)&KS,  g_KS);

    cudaFuncSetAttribute(gemm_mma<1,0>, cudaFuncAttributeMaxDynamicSharedMemorySize, SMEM_G);
    cudaFuncSetAttribute(gemm_mma<0,0>, cudaFuncAttributeMaxDynamicSharedMemorySize, SMEM_G);
    cudaFuncSetAttribute(gemm_mma<2,1>, cudaFuncAttributeMaxDynamicSharedMemorySize, SMEM_G);

    const dim3 tb(32, 8);
    const size_t M1 = (size_t)DM * DM;
    const dim3 gD(DM / BN, MS / BM);      // (8, 64)
    const dim3 gF1(DFF_ / BN, MS / BM);   // (32, 64)

    // ---- prologue ordered so launch index 5 is a gemm_mma (ncu -s 5 -c 1) ----
    // 0: copy_split
    copy_split_kernel<<<(MS * DM) / 1024, 256>>>(x, X, Xh, Xl);
    // 1-4: layer-0 QKVO weight tsplits
    {
        size_t base = 0;
        tsplit_kernel<<<dim3(DM/32, DM/32), tb>>>(Wq, Wh + base,        Wl + base,        DM, DM);
        tsplit_kernel<<<dim3(DM/32, DM/32), tb>>>(Wk, Wh + base + M1,   Wl + base + M1,   DM, DM);
        tsplit_kernel<<<dim3(DM/32, DM/32), tb>>>(Wv, Wh + base + 2*M1, Wl + base + 2*M1, DM, DM);
        tsplit_kernel<<<dim3(DM/32, DM/32), tb>>>(Wo, Wh + base + 3*M1, Wl + base + 3*M1, DM, DM);
    }
    // 5-7: layer-0 Q/K/V GEMMs (launch 5 = profiled)
    gemm_mma<1,0><<<gD, GT, SMEM_G>>>(Xh, Xl, Wh, Wl, bq, Q,  0, 0, MS, DM, DM);
    gemm_mma<1,0><<<gD, GT, SMEM_G>>>(Xh, Xl, Wh + M1, Wl + M1, bk, Kf, 0, 0, MS, DM, DM);
    gemm_mma<0,0><<<gD, GT, SMEM_G>>>(Xh, Xl, Wh + 2*M1, Wl + 2*M1, bv, Vf, 0, 0, MS, DM, DM);
    // layer-0 FFN tsplits + all remaining layers' tsplits
    tsplit_kernel<<<dim3(DFF_/32, DM/32), tb>>>(W1, Wh + 4*M1, Wl + 4*M1, DM,  DFF_);
    tsplit_kernel<<<dim3(DM/32, DFF_/32), tb>>>(W2, Wh + 8*M1, Wl + 8*M1, DFF_, DM);
    for (int l = 1; l < LNUM; l++) {
        size_t base = (size_t)l * WL_;
        tsplit_kernel<<<dim3(DM/32, DM/32),  tb>>>(Wq + l*M1, Wh + base,        Wl + base,        DM,  DM);
        tsplit_kernel<<<dim3(DM/32, DM/32),  tb>>>(Wk + l*M1, Wh + base + M1,   Wl + base + M1,   DM,  DM);
        tsplit_kernel<<<dim3(DM/32, DM/32),  tb>>>(Wv + l*M1, Wh + base + 2*M1, Wl + base + 2*M1, DM,  DM);
        tsplit_kernel<<<dim3(DM/32, DM/32),  tb>>>(Wo + l*M1, Wh + base + 3*M1, Wl + base + 3*M1, DM,  DM);
        tsplit_kernel<<<dim3(DFF_/32, DM/32), tb>>>(W1 + (size_t)l*DM*DFF_, Wh + base + 4*M1, Wl + base + 4*M1, DM,  DFF_);
        tsplit_kernel<<<dim3(DM/32, DFF_/32), tb>>>(W2 + (size_t)l*DFF_*DM, Wh + base + 8*M1, Wl + base + 8*M1, DFF_, DM);
    }

    for (int l = 0; l < LNUM; l++) {
        const size_t base = (size_t)l * WL_;
        const __nv_bfloat16 *wqh = Wh + base,        *wql = Wl + base;
        const __nv_bfloat16 *wkh = Wh + base + M1,   *wkl = Wl + base + M1;
        const __nv_bfloat16 *wvh = Wh + base + 2*M1, *wvl = Wl + base + 2*M1;
        const __nv_bfloat16 *woh = Wh + base + 3*M1, *wol = Wl + base + 3*M1;
        const __nv_bfloat16 *w1h = Wh + base + 4*M1, *w1l = Wl + base + 4*M1;
        const __nv_bfloat16 *w2h = Wh + base + 8*M1, *w2l = Wl + base + 8*M1;
        const float* bqL = bq + (size_t)l * DM;
        const float* bkL = bk + (size_t)l * DM;
        const float* bvL = bv + (size_t)l * DM;
        const float* boL = bo + (size_t)l * DM;
        const float* b1L = b1 + (size_t)l * DFF_;
        const float* b2L = b2 + (size_t)l * DM;

        // Q/K/V GEMMs (layer 0 already launched in the prologue)
        if (l > 0) {
            gemm_mma<1,0><<<gD, GT, SMEM_G>>>(Xh, Xl, wqh, wql, bqL, Q,  0, 0, MS, DM, DM);
            gemm_mma<1,0><<<gD, GT, SMEM_G>>>(Xh, Xl, wkh, wkl, bkL, Kf, 0, 0, MS, DM, DM);
            gemm_mma<0,0><<<gD, GT, SMEM_G>>>(Xh, Xl, wvh, wvl, bvL, Vf, 0, 0, MS, DM, DM);
        }

        // kv / ksum (2-stage deterministic reduce)
        kv_part_kernel<<<dim3(BSZ * HH, NCH), 256>>>(Kf, Vf, KVp, KSp);
        kv_final_kernel<<<BSZ * HH, 256>>>(KVp, KSp, KV, KS);

        // attn out (pre-projection), split bf16 -> (Th, Tl)
        attn_out_kernel<<<dim3(BSZ * HH, SSZ / 64), 256>>>(Q, KV, KS, Th, Tl);

        // projection -> Vf (fp32), then X = LN1(X + Vf), split -> (Xh, Xl)
        gemm_mma<0,0><<<gD, GT, SMEM_G>>>(Th, Tl, woh, wol, boL, Vf, 0, 0, MS, DM, DM);
        ln_kernel<<<MS, 256>>>(X, Vf, ln1w + (size_t)l*DM, ln1b + (size_t)l*DM, X, Xh, Xl, 1, 1);

        // FFN: (Fh,Fl) = split(relu(X W1 + b1)); T = F W2 + b2; X = LN2(X + T)
        gemm_mma<2,1><<<gF1, GT, SMEM_G>>>(Xh, Xl, w1h, w1l, b1L, 0, Fh, Fl, MS, DFF_, DM);
        gemm_mma<0,0><<<gD,  GT, SMEM_G>>>(Fh, Fl, w2h, w2l, b2L, T, 0, 0,  MS, DM, DFF_);
        ln_kernel<<<MS, 256>>>(X, T, ln2w + (size_t)l*DM, ln2b + (size_t)l*DM, X, Xh, Xl, 1, 1);
    }

    // final LayerNorm -> d_out (fp32, no split)
    ln_kernel<<<MS, 256>>>(X, X, lnfw, lnfb, (float*)d_out, 0, 0, 0, 0);
}

// round 17
// speedup vs baseline: 2.7135x; 1.0411x over previous
#include <cuda_runtime.h>
#include <cuda_bf16.h>
#include <math.h>
#include <stdint.h>

// Problem constants
#define BSZ   4
#define SSZ   2048
#define DM    1024
#define HH    16
#define DHD   64
#define DFF_  4096
#define LNUM  6
#define MS    (BSZ*SSZ)   // 8192 rows

// GEMM tiling (mma.sync path; tcgen05 not available via compute_103 toolchain)
// CTA tile 128(M) x 256(N) x 32(K); 8 warps, warp grid 2(M) x 4(N), warp tile 64x64.
#define BM 128
#define BN 256
#define BK 32
#define GT 256
#define NSTG 3
#define STG_BYTES 49152        // Ah 8K + Al 8K + Bh 16K + Bl 16K
#define OFF_AH 0
#define OFF_AL 8192
#define OFF_BH 16384
#define OFF_BL 32768
#define BIAS_BYTES 1024
#define SMEM_G (BIAS_BYTES + NSTG*STG_BYTES)   // 148480 B

// ---------------------------------------------------------------------------
// Scratch (device globals — no allocation allowed)
// ---------------------------------------------------------------------------
__device__ float g_X[MS*DM];                 // residual stream fp32
__device__ float g_Q[MS*DM];
__device__ float g_K[MS*DM];
__device__ float g_V[MS*DM];
__device__ float g_T[MS*DM];
__device__ __nv_bfloat16 g_Xh[MS*DM];
__device__ __nv_bfloat16 g_Xl[MS*DM];
__device__ __nv_bfloat16 g_Th[MS*DM];
__device__ __nv_bfloat16 g_Tl[MS*DM];
__device__ __nv_bfloat16 g_Fh[(size_t)MS*DFF_];
__device__ __nv_bfloat16 g_Fl[(size_t)MS*DFF_];
// transposed+split weights: per layer [q,k,v,o: 1M each][w1T: 4M][w2T: 4M]
#define WL_ (12u*1024u*1024u)
__device__ __nv_bfloat16 g_Wh[(size_t)LNUM*WL_];
__device__ __nv_bfloat16 g_Wl[(size_t)LNUM*WL_];
// attention
#define NCH 8
__device__ float g_KVp[(size_t)NCH*BSZ*HH*DHD*DHD];
__device__ float g_KSp[NCH*BSZ*HH*DHD];
__device__ float g_KV[BSZ*HH*DHD*DHD];
__device__ float g_KS[BSZ*HH*DHD];

// ---------------------------------------------------------------------------
// PTX helpers (sm_80-baseline: compile for compute_103)
// ---------------------------------------------------------------------------
__device__ __forceinline__ uint32_t smem_u32(const void* p) {
    uint32_t a;
    asm("{ .reg .u64 t; cvta.to.shared.u64 t, %1; cvt.u32.u64 %0, t; }"
        : "=r"(a) : "l"(p));
    return a;
}

#define CP_ASYNC16(s, g) \
    asm volatile("cp.async.cg.shared.global [%0], [%1], 16;" :: "r"(s), "l"(g))
#define CP_COMMIT()   asm volatile("cp.async.commit_group;")
#define CP_WAIT(n)    asm volatile("cp.async.wait_group %0;" :: "n"(n))

#define LDSM4(r0, r1, r2, r3, a) \
    asm volatile("ldmatrix.sync.aligned.m8n8.x4.shared.b16 {%0,%1,%2,%3}, [%4];" \
                 : "=r"(r0), "=r"(r1), "=r"(r2), "=r"(r3) : "r"(a))

#define MMA16816(d, a, b) \
    asm volatile("mma.sync.aligned.m16n8k16.row.col.f32.bf16.bf16.f32 " \
                 "{%0,%1,%2,%3}, {%4,%5,%6,%7}, {%8,%9}, {%0,%1,%2,%3};" \
                 : "+f"((d)[0]), "+f"((d)[1]), "+f"((d)[2]), "+f"((d)[3]) \
                 : "r"((a)[0]), "r"((a)[1]), "r"((a)[2]), "r"((a)[3]), \
                   "r"((b)[0]), "r"((b)[1]))

// swizzled smem address: rows of 64 B (4 x 16B chunks), chunk ^= (row>>1)&3
// -> conflict-free for cp.async stores and ldmatrix reads (verified R15/R16)
__device__ __forceinline__ uint32_t swz(uint32_t base, int row, int c) {
    return base + (row << 6) + (((c ^ ((row >> 1) & 3)) & 3) << 4);
}

__device__ __forceinline__ void split1(float v, __nv_bfloat16& h, __nv_bfloat16& l) {
    h = __float2bfloat16(v);
    l = __float2bfloat16(v - __bfloat162float(h));
}

// ---------------------------------------------------------------------------
// copy x -> g_X + split to g_Xh/g_Xl
// ---------------------------------------------------------------------------
__global__ void __launch_bounds__(256) copy_split_kernel(
    const float* __restrict__ src, float* __restrict__ dst,
    __nv_bfloat16* __restrict__ dh, __nv_bfloat16* __restrict__ dl)
{
    size_t i = ((size_t)blockIdx.x * 256 + threadIdx.x) * 4;
    float4 v = *(const float4*)(src + i);
    *(float4*)(dst + i) = v;
    alignas(8) __nv_bfloat16 hb[4], lb[4];
    split1(v.x, hb[0], lb[0]); split1(v.y, hb[1], lb[1]);
    split1(v.z, hb[2], lb[2]); split1(v.w, hb[3], lb[3]);
    *(uint2*)(dh + i) = *(uint2*)hb;
    *(uint2*)(dl + i) = *(uint2*)lb;
}

// ---------------------------------------------------------------------------
// weight transpose + split: W[K,N] fp32 -> Oh/Ol [N,K] bf16
// ---------------------------------------------------------------------------
__global__ void __launch_bounds__(256) tsplit_kernel(
    const float* __restrict__ W, __nv_bfloat16* __restrict__ Oh,
    __nv_bfloat16* __restrict__ Ol, int K, int N)
{
    __shared__ float t[32][33];
    const int k0 = blockIdx.y * 32, n0 = blockIdx.x * 32;
    const int tx = threadIdx.x, ty = threadIdx.y;    // 32 x 8
#pragma unroll
    for (int i = 0; i < 4; i++)
        t[ty + 8 * i][tx] = W[(size_t)(k0 + ty + 8 * i) * N + n0 + tx];
    __syncthreads();
#pragma unroll
    for (int i = 0; i < 4; i++) {
        const int n = n0 + ty + 8 * i;
        float v = t[tx][ty + 8 * i];
        __nv_bfloat16 h, l; split1(v, h, l);
        Oh[(size_t)n * K + k0 + tx] = h;
        Ol[(size_t)n * K + k0 + tx] = l;
    }
}

// ---------------------------------------------------------------------------
// bf16x3 GEMM via mma.sync: C[M,N] = act(A @ B^T + bias)
// A = Ah+Al [M,K] bf16 row-major; B = Bh+Bl [N,K] bf16 row-major
// ACT: 0 none, 1 elu+1, 2 relu.  OUT: 0 fp32 C, 1 split bf16 (Ch,Cl)
// ---------------------------------------------------------------------------
template<int ACT, int OUT>
__global__ void __launch_bounds__(GT, 1) gemm_mma(
    const __nv_bfloat16* __restrict__ Ah, const __nv_bfloat16* __restrict__ Al,
    const __nv_bfloat16* __restrict__ Bh, const __nv_bfloat16* __restrict__ Bl,
    const float* __restrict__ bias,
    float* __restrict__ C, __nv_bfloat16* __restrict__ Ch, __nv_bfloat16* __restrict__ Cl,
    int M, int N, int K)
{
    extern __shared__ char smem[];
    const uint32_t sb = smem_u32(smem);
    const uint32_t sData = sb + BIAS_BYTES;
    const int tid  = threadIdx.x;
    const int wid  = tid >> 5;
    const int lane = tid & 31;
    const int wm   = wid & 1;          // M warp coord (tiles of 64)
    const int wn   = wid >> 1;         // N warp coord (tiles of 64)
    const int m0   = blockIdx.y * BM;
    const int n0   = blockIdx.x * BN;

    ((float*)smem)[tid] = bias[n0 + tid];   // 256 floats

    const int NC = K >> 5;             // K / 32 chunks

    // ---- stage loader: 3072 x 16B chunks, 12 per thread ----
    auto load_stage = [&](int s, int c) {
        const uint32_t stg = sData + s * STG_BYTES;
        const int kc = c << 5;
#pragma unroll
        for (int it = 0; it < 12; it++) {
            const int id = tid + it * GT;          // 0..3071
            const __nv_bfloat16* g;
            uint32_t sa;
            if (id < 1024) {                       // A: 128 rows x 4 chunks, hi|lo
                const int w = id & 511;
                const int row = w >> 2, cc = w & 3;
                g = ((id < 512) ? Ah : Al) + (size_t)(m0 + row) * K + kc + cc * 8;
                sa = swz(stg + ((id < 512) ? OFF_AH : OFF_AL), row, cc);
            } else {                               // B: 256 rows x 4 chunks, hi|lo
                const int id2 = id - 1024;
                const int w = id2 & 1023;
                const int row = w >> 2, cc = w & 3;
                g = ((id2 < 1024) ? Bh : Bl) + (size_t)(n0 + row) * K + kc + cc * 8;
                sa = swz(stg + ((id2 < 1024) ? OFF_BH : OFF_BL), row, cc);
            }
            CP_ASYNC16(sa, g);
        }
    };

    load_stage(0, 0); CP_COMMIT();
    load_stage(1, 1); CP_COMMIT();

    float acc[4][8][4];
#pragma unroll
    for (int mt = 0; mt < 4; mt++)
#pragma unroll
        for (int j = 0; j < 8; j++)
#pragma unroll
            for (int q = 0; q < 4; q++) acc[mt][j][q] = 0.f;

    // fragment geometry
    const int arow = wm * 64 + (lane & 15);                      // + mt*16
    const int acol = lane >> 4;                                  // + kk*2
    const int brow = wn * 64 + ((lane >> 4) << 3) + (lane & 7);  // + p*16
    const int bcol = (lane >> 3) & 1;                            // + kk*2

    for (int c = 0; c < NC; c++) {
        CP_WAIT(1);
        __syncthreads();
        if (c + 2 < NC) load_stage((c + 2) % NSTG, c + 2);
        CP_COMMIT();

        const uint32_t stg = sData + (c % NSTG) * STG_BYTES;
#pragma unroll
        for (int kk = 0; kk < 2; kk++) {
            const int kc8 = kk * 2;
            uint32_t ah[4][4], al[4][4];
#pragma unroll
            for (int mt = 0; mt < 4; mt++) {
                const int r = arow + mt * 16;
                const int cA = kc8 + acol;
                LDSM4(ah[mt][0], ah[mt][1], ah[mt][2], ah[mt][3], swz(stg + OFF_AH, r, cA));
                LDSM4(al[mt][0], al[mt][1], al[mt][2], al[mt][3], swz(stg + OFF_AL, r, cA));
            }
            // B loaded pairwise (2 n8 frags per LDSM4) to bound live registers
#pragma unroll
            for (int p = 0; p < 4; p++) {
                const int r = brow + p * 16;
                const int cB = kc8 + bcol;
                uint32_t bh[2][2], bl[2][2];
                uint32_t t0, t1, t2, t3;
                LDSM4(t0, t1, t2, t3, swz(stg + OFF_BH, r, cB));
                bh[0][0] = t0; bh[0][1] = t1; bh[1][0] = t2; bh[1][1] = t3;
                LDSM4(t0, t1, t2, t3, swz(stg + OFF_BL, r, cB));
                bl[0][0] = t0; bl[0][1] = t1; bl[1][0] = t2; bl[1][1] = t3;
                // three sweeps; dependent MMAs on one acc are 8 apart
#pragma unroll
                for (int mt = 0; mt < 4; mt++)
#pragma unroll
                    for (int j = 0; j < 2; j++)
                        MMA16816(acc[mt][p * 2 + j], ah[mt], bh[j]);
#pragma unroll
                for (int mt = 0; mt < 4; mt++)
#pragma unroll
                    for (int j = 0; j < 2; j++)
                        MMA16816(acc[mt][p * 2 + j], ah[mt], bl[j]);
#pragma unroll
                for (int mt = 0; mt < 4; mt++)
#pragma unroll
                    for (int j = 0; j < 2; j++)
                        MMA16816(acc[mt][p * 2 + j], al[mt], bh[j]);
            }
        }
    }

    // ---- epilogue: bias + act, write fp32 or split bf16 ----
    const float* bsm = (const float*)smem;
#pragma unroll
    for (int mt = 0; mt < 4; mt++) {
#pragma unroll
        for (int j = 0; j < 8; j++) {
            const int col = wn * 64 + j * 8 + (lane & 3) * 2;
            const float b0 = bsm[col], b1 = bsm[col + 1];
            const int gcol = n0 + col;
#pragma unroll
            for (int half = 0; half < 2; half++) {
                const int grow = m0 + wm * 64 + mt * 16 + (lane >> 2) + half * 8;
                float v0 = acc[mt][j][half * 2 + 0] + b0;
                float v1 = acc[mt][j][half * 2 + 1] + b1;
                if (ACT == 1) {
                    v0 = (v0 > 0.f) ? (v0 + 1.f) : __expf(v0);
                    v1 = (v1 > 0.f) ? (v1 + 1.f) : __expf(v1);
                }
                if (ACT == 2) { v0 = fmaxf(v0, 0.f); v1 = fmaxf(v1, 0.f); }
                if (OUT == 0) {
                    float2 o; o.x = v0; o.y = v1;
                    *(float2*)(C + (size_t)grow * N + gcol) = o;
                } else {
                    alignas(4) __nv_bfloat16 h2[2], l2[2];
                    split1(v0, h2[0], l2[0]);
                    split1(v1, h2[1], l2[1]);
                    *(uint32_t*)(Ch + (size_t)grow * N + gcol) = *(uint32_t*)h2;
                    *(uint32_t*)(Cl + (size_t)grow * N + gcol) = *(uint32_t*)l2;
                }
            }
        }
    }
}

// ---------------------------------------------------------------------------
// kv partial: grid (64, NCH). Each block: 256 s-rows of one (b,h).
// ---------------------------------------------------------------------------
__global__ void __launch_bounds__(256) kv_part_kernel(
    const float* __restrict__ Kx, const float* __restrict__ Vx,
    float* __restrict__ KVp, float* __restrict__ KSp)
{
    const int bh = blockIdx.x;
    const int ch = blockIdx.y;
    const int b = bh >> 4, h = bh & 15;
    const int sbeg = ch * (SSZ / NCH);
    const float* Kb = Kx + (size_t)b * SSZ * DM + h * DHD;
    const float* Vb = Vx + (size_t)b * SSZ * DM + h * DHD;

    __shared__ float ks[32][64];
    __shared__ float vs[32][64];

    const int tid = threadIdx.x;
    const int ty = tid >> 4, tx = tid & 15;

    float acc[4][4] = {};
    float ksum = 0.f;

    for (int s0 = sbeg; s0 < sbeg + SSZ / NCH; s0 += 32) {
#pragma unroll
        for (int j = 0; j < 2; j++) {
            int idx = tid + j * 256;
            int r = idx >> 4, c4 = (idx & 15) * 4;
            *(float4*)&ks[r][c4] = *(const float4*)(Kb + (size_t)(s0 + r) * DM + c4);
            *(float4*)&vs[r][c4] = *(const float4*)(Vb + (size_t)(s0 + r) * DM + c4);
        }
        __syncthreads();
#pragma unroll 8
        for (int s = 0; s < 32; s++) {
            float a[4], bv[4];
#pragma unroll
            for (int i = 0; i < 4; i++) a[i] = ks[s][ty * 4 + i];
#pragma unroll
            for (int j = 0; j < 4; j++) bv[j] = vs[s][tx * 4 + j];
#pragma unroll
            for (int i = 0; i < 4; i++)
#pragma unroll
                for (int j = 0; j < 4; j++)
                    acc[i][j] = fmaf(a[i], bv[j], acc[i][j]);
        }
        if (tid < 64) {
#pragma unroll 8
            for (int s = 0; s < 32; s++) ksum += ks[s][tid];
        }
        __syncthreads();
    }

    float* KVb = KVp + ((size_t)ch * 64 + bh) * DHD * DHD;
#pragma unroll
    for (int i = 0; i < 4; i++)
#pragma unroll
        for (int j = 0; j < 4; j++)
            KVb[(ty * 4 + i) * DHD + tx * 4 + j] = acc[i][j];
    if (tid < 64) KSp[(ch * 64 + bh) * DHD + tid] = ksum;
}

__global__ void __launch_bounds__(256) kv_final_kernel(
    const float* __restrict__ KVp, const float* __restrict__ KSp,
    float* __restrict__ KV, float* __restrict__ KS)
{
    const int bh = blockIdx.x;
    const int tid = threadIdx.x;
    float a[16] = {};
#pragma unroll
    for (int p = 0; p < NCH; p++) {
        const float* src = KVp + ((size_t)p * 64 + bh) * 4096 + tid * 16;
#pragma unroll
        for (int j = 0; j < 16; j++) a[j] += src[j];
    }
    float* dst = KV + (size_t)bh * 4096 + tid * 16;
#pragma unroll
    for (int j = 0; j < 16; j++) dst[j] = a[j];
    if (tid < 64) {
        float s = 0.f;
#pragma unroll
        for (int p = 0; p < NCH; p++) s += KSp[(p * 64 + bh) * DHD + tid];
        KS[bh * DHD + tid] = s;
    }
}

// ---------------------------------------------------------------------------
// attn out: o = z * (q @ kv); writes split bf16 (Th, Tl)
// ---------------------------------------------------------------------------
__global__ void __launch_bounds__(256) attn_out_kernel(
    const float* __restrict__ Qx, const float* __restrict__ KVi,
    const float* __restrict__ KSi,
    __nv_bfloat16* __restrict__ Oh, __nv_bfloat16* __restrict__ Ol)
{
    const int bh = blockIdx.x;
    const int b = bh >> 4, h = bh & 15;
    const int s0 = blockIdx.y * 64;

    __shared__ float qs[64][64];
    __shared__ float kvs[64][64];
    __shared__ float kss[64];

    const int tid = threadIdx.x;
    const float* Qb  = Qx + (size_t)(b * SSZ + s0) * DM + h * DHD;
    const float* KVb = KVi + (size_t)bh * DHD * DHD;

#pragma unroll
    for (int j = 0; j < 4; j++) {
        int idx = tid + j * 256;
        int r = idx >> 4, c4 = (idx & 15) * 4;
        *(float4*)&qs[r][c4]  = *(const float4*)(Qb + (size_t)r * DM + c4);
        *(float4*)&kvs[r][c4] = *(const float4*)(KVb + r * DHD + c4);
    }
    if (tid < 64) kss[tid] = KSi[bh * DHD + tid];
    __syncthreads();

    const int row = tid >> 2;
    const int mo  = (tid & 3) * 16;

    float z = 0.f;
#pragma unroll
    for (int d = 0; d < 64; d++) z = fmaf(qs[row][d], kss[d], z);
    z = 1.f / (z + 1e-6f);

    float acc[16] = {};
#pragma unroll
    for (int d = 0; d < 64; d++) {
        float qd = qs[row][d];
#pragma unroll
        for (int m = 0; m < 16; m++)
            acc[m] = fmaf(qd, kvs[d][mo + m], acc[m]);
    }

    alignas(16) __nv_bfloat16 hb[16], lb[16];
#pragma unroll
    for (int m = 0; m < 16; m++) split1(acc[m] * z, hb[m], lb[m]);
    const size_t base = (size_t)(b * SSZ + s0 + row) * DM + h * DHD + mo;
    *(uint4*)(Oh + base)     = ((uint4*)hb)[0];
    *(uint4*)(Oh + base + 8) = ((uint4*)hb)[1];
    *(uint4*)(Ol + base)     = ((uint4*)lb)[0];
    *(uint4*)(Ol + base + 8) = ((uint4*)lb)[1];
}

// ---------------------------------------------------------------------------
// LayerNorm(X (+ Y)); writes fp32 out and (optionally) split bf16 out
// ---------------------------------------------------------------------------
__global__ void __launch_bounds__(256) ln_kernel(
    const float* X, const float* Yr, const float* __restrict__ w,
    const float* __restrict__ bb, float* out,
    __nv_bfloat16* oh, __nv_bfloat16* ol, int has_res, int do_split)
{
    __shared__ float ss[8], ssq[8];
    __shared__ float sm, sr;

    const int row = blockIdx.x;
    const int tid = threadIdx.x;
    const int c = tid * 4;

    float4 xv = *(const float4*)(X + (size_t)row * DM + c);
    float v0 = xv.x, v1 = xv.y, v2 = xv.z, v3 = xv.w;
    if (has_res) {
        float4 yv = *(const float4*)(Yr + (size_t)row * DM + c);
        v0 += yv.x; v1 += yv.y; v2 += yv.z; v3 += yv.w;
    }

    float s  = v0 + v1 + v2 + v3;
    float sq = v0 * v0 + v1 * v1 + v2 * v2 + v3 * v3;
#pragma unroll
    for (int off = 16; off; off >>= 1) {
        s  += __shfl_xor_sync(0xffffffffu, s,  off);
        sq += __shfl_xor_sync(0xffffffffu, sq, off);
    }
    const int wid = tid >> 5, lane = tid & 31;
    if (lane == 0) { ss[wid] = s; ssq[wid] = sq; }
    __syncthreads();
    if (tid == 0) {
        float t = 0.f, tq = 0.f;
#pragma unroll
        for (int i = 0; i < 8; i++) { t += ss[i]; tq += ssq[i]; }
        float mean = t * (1.f / DM);
        float var  = tq * (1.f / DM) - mean * mean;
        sm = mean;
        sr = rsqrtf(var + 1e-5f);
    }
    __syncthreads();
    const float mean = sm, rstd = sr;

    float4 wv = *(const float4*)(w + c);
    float4 bv = *(const float4*)(bb + c);
    float4 ov;
    ov.x = (v0 - mean) * rstd * wv.x + bv.x;
    ov.y = (v1 - mean) * rstd * wv.y + bv.y;
    ov.z = (v2 - mean) * rstd * wv.z + bv.z;
    ov.w = (v3 - mean) * rstd * wv.w + bv.w;
    *(float4*)(out + (size_t)row * DM + c) = ov;

    if (do_split) {
        alignas(8) __nv_bfloat16 hb[4], lb[4];
        split1(ov.x, hb[0], lb[0]); split1(ov.y, hb[1], lb[1]);
        split1(ov.z, hb[2], lb[2]); split1(ov.w, hb[3], lb[3]);
        *(uint2*)(oh + (size_t)row * DM + c) = *(uint2*)hb;
        *(uint2*)(ol + (size_t)row * DM + c) = *(uint2*)lb;
    }
}

// ---------------------------------------------------------------------------
// Orchestration
// ---------------------------------------------------------------------------
extern "C" void kernel_launch(void* const* d_in, const int* in_sizes, int n_in,
                              void* d_out, int out_size)
{
    const float* x    = (const float*)d_in[0];
    const float* Wq   = (const float*)d_in[1];
    const float* bq   = (const float*)d_in[2];
    const float* Wk   = (const float*)d_in[3];
    const float* bk   = (const float*)d_in[4];
    const float* Wv   = (const float*)d_in[5];
    const float* bv   = (const float*)d_in[6];
    const float* Wo   = (const float*)d_in[7];
    const float* bo   = (const float*)d_in[8];
    const float* ln1w = (const float*)d_in[9];
    const float* ln1b = (const float*)d_in[10];
    const float* W1   = (const float*)d_in[11];
    const float* b1   = (const float*)d_in[12];
    const float* W2   = (const float*)d_in[13];
    const float* b2   = (const float*)d_in[14];
    const float* ln2w = (const float*)d_in[15];
    const float* ln2b = (const float*)d_in[16];
    const float* lnfw = (const float*)d_in[17];
    const float* lnfb = (const float*)d_in[18];

    float *X, *Q, *Kf, *Vf, *T, *KVp, *KSp, *KV, *KS;
    __nv_bfloat16 *Xh, *Xl, *Th, *Tl, *Fh, *Fl, *Wh, *Wl;
    cudaGetSymbolAddress((void**)&X,   g_X);
    cudaGetSymbolAddress((void**)&Q,   g_Q);
    cudaGetSymbolAddress((void**)&Kf,  g_K);
    cudaGetSymbolAddress((void**)&Vf,  g_V);
    cudaGetSymbolAddress((void**)&T,   g_T);
    cudaGetSymbolAddress((void**)&Xh,  g_Xh);
    cudaGetSymbolAddress((void**)&Xl,  g_Xl);
    cudaGetSymbolAddress((void**)&Th,  g_Th);
    cudaGetSymbolAddress((void**)&Tl,  g_Tl);
    cudaGetSymbolAddress((void**)&Fh,  g_Fh);
    cudaGetSymbolAddress((void**)&Fl,  g_Fl);
    cudaGetSymbolAddress((void**)&Wh,  g_Wh);
    cudaGetSymbolAddress((void**)&Wl,  g_Wl);
    cudaGetSymbolAddress((void**)&KVp, g_KVp);
    cudaGetSymbolAddress((void**)&KSp, g_KSp);
    cudaGetSymbolAddress((void**)&KV,  g_KV);
    cudaGetSymbolAddress((void**)&KS,  g_KS);

    cudaFuncSetAttribute(gemm_mma<1,0>, cudaFuncAttributeMaxDynamicSharedMemorySize, SMEM_G);
    cudaFuncSetAttribute(gemm_mma<0,0>, cudaFuncAttributeMaxDynamicSharedMemorySize, SMEM_G);
    cudaFuncSetAttribute(gemm_mma<2,1>, cudaFuncAttributeMaxDynamicSharedMemorySize, SMEM_G);

    const dim3 tb(32, 8);
    const size_t M1 = (size_t)DM * DM;
    const dim3 gD(DM / BN, MS / BM);      // (4, 64)
    const dim3 gF1(DFF_ / BN, MS / BM);   // (16, 64)

    // ---- prologue ordered so harness+mine launch #4/#5 are gemm_mma ----
    // (R15/R16 evidence: ncu's captured launch == my launch index 4)
    copy_split_kernel<<<(MS * DM) / 1024, 256>>>(x, X, Xh, Xl);                       // 0
    tsplit_kernel<<<dim3(DM/32, DM/32), tb>>>(Wq, Wh,        Wl,        DM, DM);      // 1
    tsplit_kernel<<<dim3(DM/32, DM/32), tb>>>(Wk, Wh + M1,   Wl + M1,   DM, DM);      // 2
    gemm_mma<1,0><<<gD, GT, SMEM_G>>>(Xh, Xl, Wh, Wl, bq, Q,  0, 0, MS, DM, DM);      // 3
    gemm_mma<1,0><<<gD, GT, SMEM_G>>>(Xh, Xl, Wh + M1, Wl + M1, bk, Kf, 0, 0, MS, DM, DM); // 4
    tsplit_kernel<<<dim3(DM/32, DM/32), tb>>>(Wv, Wh + 2*M1, Wl + 2*M1, DM, DM);      // 5
    gemm_mma<0,0><<<gD, GT, SMEM_G>>>(Xh, Xl, Wh + 2*M1, Wl + 2*M1, bv, Vf, 0, 0, MS, DM, DM); // 6
    tsplit_kernel<<<dim3(DM/32, DM/32), tb>>>(Wo, Wh + 3*M1, Wl + 3*M1, DM, DM);
    tsplit_kernel<<<dim3(DFF_/32, DM/32), tb>>>(W1, Wh + 4*M1, Wl + 4*M1, DM,  DFF_);
    tsplit_kernel<<<dim3(DM/32, DFF_/32), tb>>>(W2, Wh + 8*M1, Wl + 8*M1, DFF_, DM);
    for (int l = 1; l < LNUM; l++) {
        size_t base = (size_t)l * WL_;
        tsplit_kernel<<<dim3(DM/32, DM/32),  tb>>>(Wq + l*M1, Wh + base,        Wl + base,        DM,  DM);
        tsplit_kernel<<<dim3(DM/32, DM/32),  tb>>>(Wk + l*M1, Wh + base + M1,   Wl + base + M1,   DM,  DM);
        tsplit_kernel<<<dim3(DM/32, DM/32),  tb>>>(Wv + l*M1, Wh + base + 2*M1, Wl + base + 2*M1, DM,  DM);
        tsplit_kernel<<<dim3(DM/32, DM/32),  tb>>>(Wo + l*M1, Wh + base + 3*M1, Wl + base + 3*M1, DM,  DM);
        tsplit_kernel<<<dim3(DFF_/32, DM/32), tb>>>(W1 + (size_t)l*DM*DFF_, Wh + base + 4*M1, Wl + base + 4*M1, DM,  DFF_);
        tsplit_kernel<<<dim3(DM/32, DFF_/32), tb>>>(W2 + (size_t)l*DFF_*DM, Wh + base + 8*M1, Wl + base + 8*M1, DFF_, DM);
    }

    for (int l = 0; l < LNUM; l++) {
        const size_t base = (size_t)l * WL_;
        const __nv_bfloat16 *wqh = Wh + base,        *wql = Wl + base;
        const __nv_bfloat16 *wkh = Wh + base + M1,   *wkl = Wl + base + M1;
        const __nv_bfloat16 *wvh = Wh + base + 2*M1, *wvl = Wl + base + 2*M1;
        const __nv_bfloat16 *woh = Wh + base + 3*M1, *wol = Wl + base + 3*M1;
        const __nv_bfloat16 *w1h = Wh + base + 4*M1, *w1l = Wl + base + 4*M1;
        const __nv_bfloat16 *w2h = Wh + base + 8*M1, *w2l = Wl + base + 8*M1;
        const float* bqL = bq + (size_t)l * DM;
        const float* bkL = bk + (size_t)l * DM;
        const float* bvL = bv + (size_t)l * DM;
        const float* boL = bo + (size_t)l * DM;
        const float* b1L = b1 + (size_t)l * DFF_;
        const float* b2L = b2 + (size_t)l * DM;

        // Q/K/V GEMMs (layer 0 already launched in the prologue)
        if (l > 0) {
            gemm_mma<1,0><<<gD, GT, SMEM_G>>>(Xh, Xl, wqh, wql, bqL, Q,  0, 0, MS, DM, DM);
            gemm_mma<1,0><<<gD, GT, SMEM_G>>>(Xh, Xl, wkh, wkl, bkL, Kf, 0, 0, MS, DM, DM);
            gemm_mma<0,0><<<gD, GT, SMEM_G>>>(Xh, Xl, wvh, wvl, bvL, Vf, 0, 0, MS, DM, DM);
        }

        // kv / ksum (2-stage deterministic reduce)
        kv_part_kernel<<<dim3(BSZ * HH, NCH), 256>>>(Kf, Vf, KVp, KSp);
        kv_final_kernel<<<BSZ * HH, 256>>>(KVp, KSp, KV, KS);

        // attn out (pre-projection), split bf16 -> (Th, Tl)
        attn_out_kernel<<<dim3(BSZ * HH, SSZ / 64), 256>>>(Q, KV, KS, Th, Tl);

        // projection -> Vf (fp32), then X = LN1(X + Vf), split -> (Xh, Xl)
        gemm_mma<0,0><<<gD, GT, SMEM_G>>>(Th, Tl, woh, wol, boL, Vf, 0, 0, MS, DM, DM);
        ln_kernel<<<MS, 256>>>(X, Vf, ln1w + (size_t)l*DM, ln1b + (size_t)l*DM, X, Xh, Xl, 1, 1);

        // FFN: (Fh,Fl) = split(relu(X W1 + b1)); T = F W2 + b2; X = LN2(X + T)
        gemm_mma<2,1><<<gF1, GT, SMEM_G>>>(Xh, Xl, w1h, w1l, b1L, 0, Fh, Fl, MS, DFF_, DM);
        gemm_mma<0,0><<<gD,  GT, SMEM_G>>>(Fh, Fl, w2h, w2l, b2L, T, 0, 0,  MS, DM, DFF_);
        ln_kernel<<<MS, 256>>>(X, T, ln2w + (size_t)l*DM, ln2b + (size_t)l*DM, X, Xh, Xl, 1, 1);
    }

    // final LayerNorm -> d_out (fp32, no split)
    ln_kernel<<<MS, 256>>>(X, X, lnfw, lnfb, (float*)d_out, 0, 0, 0, 0);
}